// round 12
// baseline (speedup 1.0000x reference)
#include <cuda_runtime.h>
#include <cuda_fp16.h>
#include <math.h>
#include <stdint.h>

// ---------------- problem constants ----------------
#define BB   16
#define TT   2048
#define LL   512
#define HH   256
#define HH2  512
#define CVQd 64
#define NLB  10   // NL * NB
#define CINP 96   // conv_in padded channels (80 -> 96)

// ---------------- sizes (floats) ----------------
#define SZ_BHT  ((size_t)BB*HH*TT)
#define SZ_BMT  ((size_t)BB*HH2*TT)
#define SZ_XP   ((size_t)BB*CINP*TT)
#define SZ_BHL  ((size_t)BB*HH*LL)
#define SZ_SEG  ((size_t)BB*HH*(LL+1))
#define SZ_CNT  ((size_t)BB*(LL+1))
#define SZ_BZL  ((size_t)BB*CVQd*LL)

// weight plane sizes (elements)
#define WSZ_CIN ((size_t)HH*CINP)
#define WSZ_E1  ((size_t)NLB*HH2*HH*3)
#define WSZ_E2  ((size_t)NLB*HH*HH2)
#define WSZ_EP  ((size_t)HH*HH*3)
#define WSZ_PI  ((size_t)CVQd*HH)
#define WSZ_PO  ((size_t)HH*CVQd)
#define WTOT    (WSZ_CIN + 2*(WSZ_E1 + WSZ_E2 + WSZ_EP) + WSZ_PI + WSZ_PO)

// scratch offsets (float units). half planes take size/2 floats.
// ALL activation tensors are t-major: [b][t][c].
#define O_BX   ((size_t)0)
#define O_BY   (O_BX  + SZ_BHT)
#define O_BNH  (O_BY  + SZ_BHT)
#define O_BNL  (O_BNH + SZ_BHT/2)
#define O_BMH  (O_BNL + SZ_BHT/2)
#define O_BML  (O_BMH + SZ_BMT/2)
#define O_XH   (O_BML + SZ_BMT/2)
#define O_XL   (O_XH  + SZ_XP/2)
#define O_BYH  (O_XL  + SZ_XP/2)
#define O_BYL  (O_BYH + SZ_BHL/2)
#define O_SEG  (O_BYL + SZ_BHL/2)
#define O_CNT  (O_SEG + SZ_SEG)
#define O_BZ   (O_CNT + SZ_CNT)
#define O_QH   (O_BZ  + SZ_BZL)
#define O_QL   (O_QH  + SZ_BZL/2)
#define O_LOSS (O_QL  + SZ_BZL/2)
#define O_WH   (O_LOSS + 16)
#define O_WL   (O_WH  + WTOT/2)
#define SCRATCH_TOT (O_WL + WTOT/2)

__device__ __align__(16) float g_scratch[SCRATCH_TOT];

// weight offsets inside wh/wl planes (element units)
#define OW_CIN ((size_t)0)
#define OW_E1  (OW_CIN + WSZ_CIN)
#define OW_E2  (OW_E1 + WSZ_E1)
#define OW_EP  (OW_E2 + WSZ_E2)
#define OW_P1  (OW_EP + WSZ_EP)
#define OW_P2  (OW_P1 + WSZ_E1)
#define OW_PP  (OW_P2 + WSZ_E2)
#define OW_PI  (OW_PP + WSZ_EP)
#define OW_PO  (OW_PI + WSZ_PI)

// ---------------- helpers ----------------
__device__ __forceinline__ uint32_t smem_to_u32(const void* p) {
    uint32_t a;
    asm("{ .reg .u64 t; cvta.to.shared.u64 t, %1; cvt.u32.u64 %0, t; }" : "=r"(a) : "l"(p));
    return a;
}
#define CP16(dst, src) \
    asm volatile("cp.async.cg.shared.global [%0], [%1], 16;" :: "r"(dst), "l"(src))
#define CP16Z(dst, src, ssz) \
    asm volatile("cp.async.cg.shared.global [%0], [%1], 16, %2;" :: "r"(dst), "l"(src), "r"(ssz))

#define LDSM4(r0, r1, r2, r3, addr)                                              \
    asm volatile("ldmatrix.sync.aligned.m8n8.x4.shared.b16 {%0,%1,%2,%3}, [%4];" \
        : "=r"(r0), "=r"(r1), "=r"(r2), "=r"(r3) : "r"(addr))

#define MMA_F16(C, A, B)                                                         \
    asm volatile("mma.sync.aligned.m16n8k16.row.col.f32.f16.f16.f32 "            \
        "{%0,%1,%2,%3}, {%4,%5,%6,%7}, {%8,%9}, {%0,%1,%2,%3};"                  \
        : "+f"((C)[0]), "+f"((C)[1]), "+f"((C)[2]), "+f"((C)[3])                  \
        : "r"((A)[0]), "r"((A)[1]), "r"((A)[2]), "r"((A)[3]),                     \
          "r"((B)[0]), "r"((B)[1]))

__device__ __forceinline__ void split_f16(float v, __half& h, __half& l)
{
    h = __float2half_rn(v);
    l = __float2half_rn(v - __half2float(h));
}

// ---------------- merged prepass ----------------
__device__ __forceinline__ void prep_one(const float* __restrict__ w,
                                         __half* __restrict__ oh, __half* __restrict__ ol,
                                         int total, int Cout, int Cin, int KS, int idx)
{
    if (idx >= total) return;
    int per_layer = Cout * Cin * KS;
    int layer = idx / per_layer;
    int r = idx - layer * per_layer;
    int co = r / (Cin * KS);
    int r2 = r - co * (Cin * KS);
    int ci = r2 / KS;
    int tap = r2 - ci * KS;
    __half h, l;
    split_f16(w[idx], h, l);
    int kidx = (ci >> 4) * (16 * KS) + tap * 16 + (ci & 15);
    size_t o = ((size_t)layer * Cout + co) * (size_t)(Cin * KS) + kidx;
    oh[o] = h; ol[o] = l;
}

__global__ void prep_all(
    const float* __restrict__ x,
    const float* __restrict__ cinw, const float* __restrict__ e1,
    const float* __restrict__ e2,  const float* __restrict__ ep,
    const float* __restrict__ p1,  const float* __restrict__ p2,
    const float* __restrict__ pp,  const float* __restrict__ pi,
    const float* __restrict__ po,
    __half* __restrict__ wh, __half* __restrict__ wl,
    __half* __restrict__ xh, __half* __restrict__ xl)
{
    int idx = blockIdx.x * 256 + threadIdx.x;
    switch (blockIdx.y) {
    case 0:  // conv_in weights padded 80 -> 96 ci (KS=1, kidx = ci)
        if (idx < (int)WSZ_CIN) {
            int co = idx / CINP, ci = idx - co * CINP;
            float v = (ci < 80) ? cinw[co * 80 + ci] : 0.f;
            __half h, l;
            split_f16(v, h, l);
            wh[OW_CIN + idx] = h; wl[OW_CIN + idx] = l;
        }
        break;
    case 1: prep_one(e1, wh + OW_E1, wl + OW_E1, (int)WSZ_E1, HH2, HH, 3, idx); break;
    case 2: prep_one(e2, wh + OW_E2, wl + OW_E2, (int)WSZ_E2, HH, HH2, 1, idx); break;
    case 3: prep_one(ep, wh + OW_EP, wl + OW_EP, (int)WSZ_EP, HH, HH, 3, idx); break;
    case 4: prep_one(p1, wh + OW_P1, wl + OW_P1, (int)WSZ_E1, HH2, HH, 3, idx); break;
    case 5: prep_one(p2, wh + OW_P2, wl + OW_P2, (int)WSZ_E2, HH, HH2, 1, idx); break;
    case 6: prep_one(pp, wh + OW_PP, wl + OW_PP, (int)WSZ_EP, HH, HH, 3, idx); break;
    case 7: prep_one(pi, wh + OW_PI, wl + OW_PI, (int)WSZ_PI, CVQd, HH, 1, idx); break;
    case 8: prep_one(po, wh + OW_PO, wl + OW_PO, (int)WSZ_PO, HH, CVQd, 1, idx); break;
    default:  // x -> 96-channel t-major planes (zero-padded)
        if (idx < (int)SZ_XP) {
            int b = idx / (CINP * TT);
            int r = idx - b * CINP * TT;
            int t = r / CINP, c = r - t * CINP;
            float v = (c < 80) ? x[((size_t)b * 80 + c) * TT + t] : 0.f;
            __half h, l;
            split_f16(v, h, l);
            size_t o = ((size_t)b * TT + t) * CINP + c;
            xh[o] = h; xl[o] = l;
        }
        break;
    }
}

// ---------------- LayerNorm (t-major): warp per row ----------------
__global__ void ln_kernel(const float* __restrict__ in, __half* __restrict__ outh,
                          __half* __restrict__ outl,
                          const float* __restrict__ gma, const float* __restrict__ bta,
                          const float* __restrict__ mask, int Tdim)
{
    int row = blockIdx.x * 8 + (threadIdx.x >> 5);
    if (row >= BB * Tdim) return;
    int lane = threadIdx.x & 31;
    const float4* p = (const float4*)(in + (size_t)row * HH) + lane * 2;
    float4 a = p[0], q = p[1];
    float v[8] = {a.x, a.y, a.z, a.w, q.x, q.y, q.z, q.w};
    float s = 0.f, s2 = 0.f;
    #pragma unroll
    for (int i = 0; i < 8; i++) { s += v[i]; s2 += v[i] * v[i]; }
    #pragma unroll
    for (int o = 16; o; o >>= 1) {
        s  += __shfl_xor_sync(0xffffffffu, s, o);
        s2 += __shfl_xor_sync(0xffffffffu, s2, o);
    }
    float mean = s * (1.f / HH);
    float var  = s2 * (1.f / HH) - mean * mean;
    float r = rsqrtf(var + 1e-5f);
    float mk = mask ? mask[row] : 1.f;
    __half2 hv[4], lv[4];
    #pragma unroll
    for (int i = 0; i < 4; i++) {
        int c = lane * 8 + 2 * i;
        float n0 = ((v[2*i]   - mean) * r * gma[c]     + bta[c])     * mk;
        float n1 = ((v[2*i+1] - mean) * r * gma[c + 1] + bta[c + 1]) * mk;
        __half h0, l0, h1, l1;
        split_f16(n0, h0, l0);
        split_f16(n1, h1, l1);
        hv[i] = __halves2half2(h0, h1);
        lv[i] = __halves2half2(l0, l1);
    }
    *(uint4*)(outh + (size_t)row * HH + lane * 8) = *(uint4*)hv;
    *(uint4*)(outl + (size_t)row * HH + lane * 8) = *(uint4*)lv;
}

// ---------------- fp16-split mma.sync conv GEMM ----------------
// Both variants: 4-buffer cp.async pipeline, prefetch distance 3, wait_group 2,
// one __syncthreads per stage. Stage = 16 ci (one k16-step for KS=1; 3 tap-steps
// for KS=3 via ldmatrix row shifts on un-replicated X rows [tg-2, tg+128)).
template<int KS>
__global__ void __launch_bounds__(256, 2)
mma_conv(const __half* __restrict__ inh, const __half* __restrict__ inl,
         const __half* __restrict__ wh, const __half* __restrict__ wl,
         const float* __restrict__ bias,
         float* outF, int tmaj, __half* outH, __half* outL,
         const float* __restrict__ residual, const float* __restrict__ mask,
         int Cin, int Cout, int Tdim, float scale, int dogelu)
{
    extern __shared__ char smc[];
    constexpr int SXX = 24;                        // X row stride (halves), 48B
    constexpr int SXW = (KS == 3) ? 56 : 24;       // W row stride (halves)
    constexpr int XPL = ((KS == 3) ? 132 : 128) * SXX;
    constexpr int WPL = 64 * SXW;
    constexpr int BUF = 2 * (XPL + WPL);
    constexpr int NBUF = 4;

    const int b   = blockIdx.z;
    const int cog = blockIdx.y * 64;
    const int tg  = blockIdx.x * 128;
    const int tid = threadIdx.x;
    const int lane = tid & 31, wid = tid >> 5;
    const int wm = wid >> 2, wn = wid & 3;
    const int g = lane >> 2, th = lane & 3;

    const uint32_t smb = smem_to_u32(smc);
    const int Ktot = Cin * KS;
    const size_t xb = (size_t)b * Tdim * Cin;   // half units

    const int laneA = ((lane & 7) + ((lane >> 3) & 1) * 8) * SXW + (lane >> 4) * 8;
    const int laneB = ((lane & 7) + (lane >> 4) * 8) * SXX + ((lane >> 3) & 1) * 8;

    float c[2][4][4];
    #pragma unroll
    for (int i = 0; i < 2; i++)
        #pragma unroll
        for (int j = 0; j < 4; j++)
            #pragma unroll
            for (int k = 0; k < 4; k++) c[i][j][k] = 0.f;

    const int nst = Cin >> 4;

    auto load_stage = [&](int s, int buf) {
        const uint32_t bb = smb + 2u * (uint32_t)(buf * BUF);
        const int ci0 = s * 16;
        if (KS == 3) {
            // W: 2 planes x 64 rows x 6 chunks = 768
            #pragma unroll
            for (int it = 0; it < 3; it++) {
                int ic = it * 256 + tid;
                int plane = (ic >= 384) ? 1 : 0;
                int r = ic - plane * 384;
                int row = r / 6, ch = r - row * 6;
                const __half* src = (plane ? wl : wh) + (size_t)(cog + row) * Ktot + s * 48 + ch * 8;
                CP16(bb + 2u * (uint32_t)(2 * XPL + plane * WPL + row * SXW + ch * 8), src);
            }
            // X: 2 planes x 130 rows x 2 chunks = 520
            #pragma unroll
            for (int it = 0; it < 3; it++) {
                int ic = it * 256 + tid;
                if (ic < 520) {
                    int plane = (ic >= 260) ? 1 : 0;
                    int r = ic - plane * 260;
                    int u = r >> 1, ch = r & 1;
                    int gt = tg - 2 + u;
                    const __half* src = (plane ? inl : inh) + xb + (size_t)gt * Cin + ci0 + ch * 8;
                    int ssz = (gt >= 0) ? 16 : 0;
                    CP16Z(bb + 2u * (uint32_t)(plane * XPL + u * SXX + ch * 8), src, ssz);
                }
            }
        } else {
            // W: 2 planes x 64 rows x 2 chunks = 256 (single iteration)
            {
                int ic = tid;
                int plane = ic >> 7, r = ic & 127;
                int row = r >> 1, ch = r & 1;
                const __half* src = (plane ? wl : wh) + (size_t)(cog + row) * Ktot + ci0 + ch * 8;
                CP16(bb + 2u * (uint32_t)(2 * XPL + plane * WPL + row * SXW + ch * 8), src);
            }
            // X: 2 planes x 128 rows x 2 chunks = 512
            #pragma unroll
            for (int it = 0; it < 2; it++) {
                int ic = it * 256 + tid;
                int plane = ic >> 8, r = ic & 255;
                int t = r >> 1, ch = r & 1;
                const __half* src = (plane ? inl : inh) + xb + (size_t)(tg + t) * Cin + ci0 + ch * 8;
                CP16(bb + 2u * (uint32_t)(plane * XPL + t * SXX + ch * 8), src);
            }
        }
    };

    auto compute = [&](int buf) {
        const uint32_t bb = smb + 2u * (uint32_t)(buf * BUF);
        constexpr int KST = (KS == 3) ? 3 : 1;
        #pragma unroll
        for (int ks = 0; ks < KST; ks++) {
            uint32_t ah[2][4], al[2][4], bh[4][2], bl[4][2];
            #pragma unroll
            for (int mf = 0; mf < 2; mf++) {
                uint32_t base = bb + 2u * (uint32_t)(2 * XPL + (wm * 32 + mf * 16) * SXW + ks * 16 + laneA);
                LDSM4(ah[mf][0], ah[mf][1], ah[mf][2], ah[mf][3], base);
                LDSM4(al[mf][0], al[mf][1], al[mf][2], al[mf][3], base + 2u * (uint32_t)WPL);
            }
            #pragma unroll
            for (int p = 0; p < 2; p++) {
                int rowb = wn * 32 + p * 16 + ((KS == 3) ? ks : 0);
                uint32_t base = bb + 2u * (uint32_t)(rowb * SXX + laneB);
                LDSM4(bh[2*p][0], bh[2*p][1], bh[2*p+1][0], bh[2*p+1][1], base);
                LDSM4(bl[2*p][0], bl[2*p][1], bl[2*p+1][0], bl[2*p+1][1], base + 2u * (uint32_t)XPL);
            }
            #pragma unroll
            for (int mf = 0; mf < 2; mf++)
                #pragma unroll
                for (int nf = 0; nf < 4; nf++) {
                    MMA_F16(c[mf][nf], ah[mf], bh[nf]);
                    MMA_F16(c[mf][nf], ah[mf], bl[nf]);
                    MMA_F16(c[mf][nf], al[mf], bh[nf]);
                }
        }
    };

    // ---- 4-buffer pipeline, prefetch distance 3, 1 sync per stage ----
    {
        int pre = (nst < NBUF - 1) ? nst : (NBUF - 1);
        for (int p = 0; p < pre; p++) {
            load_stage(p, p);
            asm volatile("cp.async.commit_group;");
        }
    }
    for (int s = 0; s < nst; s++) {
        if (s + 2 < nst)      asm volatile("cp.async.wait_group 2;");
        else if (s + 1 < nst) asm volatile("cp.async.wait_group 1;");
        else                  asm volatile("cp.async.wait_group 0;");
        __syncthreads();
        if (s + NBUF - 1 < nst) {
            load_stage(s + NBUF - 1, (s + NBUF - 1) & 3);
            asm volatile("cp.async.commit_group;");
        }
        compute(s & 3);
    }

    // ---- epilogue ----
    #pragma unroll
    for (int mf = 0; mf < 2; mf++) {
        #pragma unroll
        for (int nf = 0; nf < 4; nf++) {
            int co0 = cog + wm * 32 + mf * 16 + g;
            int t0 = tg + wn * 32 + nf * 8 + 2 * th;
            float mk0 = mask ? mask[b * Tdim + t0] : 1.f;
            float mk1 = mask ? mask[b * Tdim + t0 + 1] : 1.f;
            #pragma unroll
            for (int half = 0; half < 2; half++) {
                int co = co0 + half * 8;
                float bi = bias[co];
                float v0 = (c[mf][nf][half * 2 + 0] + bi) * scale;
                float v1 = (c[mf][nf][half * 2 + 1] + bi) * scale;
                if (dogelu) {
                    v0 = 0.5f * v0 * (1.f + erff(v0 * 0.70710678118654752f));
                    v1 = 0.5f * v1 * (1.f + erff(v1 * 0.70710678118654752f));
                }
                size_t r0 = ((size_t)b * Tdim + t0) * Cout + co;
                size_t r1 = r0 + Cout;
                if (residual) { v0 += residual[r0]; v1 += residual[r1]; }
                if (mask) { v0 *= mk0; v1 *= mk1; }
                if (outF) {
                    if (tmaj) { outF[r0] = v0; outF[r1] = v1; }
                    else {
                        size_t o = ((size_t)b * Cout + co) * Tdim + t0;
                        outF[o] = v0; outF[o + 1] = v1;
                    }
                }
                if (outH) {
                    __half h0, l0, h1, l1;
                    split_f16(v0, h0, l0);
                    split_f16(v1, h1, l1);
                    outH[r0] = h0; outH[r1] = h1;
                    outL[r0] = l0; outL[r1] = l1;
                }
            }
        }
    }
}

// ---------------- group_by_segs (t-major) ----------------
__global__ void seg_zero(float* seg, float* cnt)
{
    int i = blockIdx.x * blockDim.x + threadIdx.x;
    if (i < (int)SZ_SEG) seg[i] = 0.f;
    if (i < (int)SZ_CNT) cnt[i] = 0.f;
}
__global__ void seg_scatter(const float* __restrict__ in, const int* __restrict__ mel2ph,
                            float* seg, float* cnt)
{
    int t = blockIdx.x, b = blockIdx.y, c = threadIdx.x;
    int ph = mel2ph[b * TT + t];
    if (ph < 1 || ph > LL) return;
    float v = in[((size_t)b * TT + t) * HH + c];
    atomicAdd(&seg[((size_t)b * (LL + 1) + ph) * HH + c], v);
    if (c == 0) atomicAdd(&cnt[b * (LL + 1) + ph], 1.f);
}
__global__ void seg_div(const float* __restrict__ seg, const float* __restrict__ cnt,
                        float* __restrict__ outg)
{
    int i = blockIdx.x * blockDim.x + threadIdx.x;   // over [b][l][c]
    if (i >= BB * LL * HH) return;
    int c = i % HH; int bl = i / HH; int l = bl % LL; int b = bl / LL;
    float s = seg[((size_t)b * (LL + 1) + l + 1) * HH + c];
    float n = fmaxf(cnt[b * (LL + 1) + l + 1], 1.f);
    outg[i] = s / n;
}

// ---------------- VQ (t-major) ----------------
__global__ void loss_init(float* loss) { if (threadIdx.x == 0) *loss = 0.f; }

__global__ void vq_kernel(const float* __restrict__ z, const float* __restrict__ cb,
                          __half* __restrict__ qh, __half* __restrict__ ql,
                          float* __restrict__ outIdx, float* loss)
{
    __shared__ float zsh[64];
    __shared__ float dsh[128];
    __shared__ int   ish[128];
    int l = blockIdx.x, b = blockIdx.y, tid = threadIdx.x;
    if (tid < 64) zsh[tid] = z[((size_t)b * LL + l) * CVQd + tid];
    __syncthreads();
    float x2 = 0.f, dot = 0.f, c2 = 0.f;
    #pragma unroll 8
    for (int c = 0; c < 64; c++) {
        float zv = zsh[c]; float cv = cb[tid * 64 + c];
        x2 += zv * zv; dot += zv * cv; c2 += cv * cv;
    }
    dsh[tid] = x2 - 2.f * dot + c2;
    ish[tid] = tid;
    __syncthreads();
    for (int s = 64; s > 0; s >>= 1) {
        if (tid < s) {
            float d2 = dsh[tid + s]; int i2 = ish[tid + s];
            if (d2 < dsh[tid] || (d2 == dsh[tid] && i2 < ish[tid])) { dsh[tid] = d2; ish[tid] = i2; }
        }
        __syncthreads();
    }
    int best = ish[0];
    __syncthreads();
    float part = 0.f;
    if (tid < 64) {
        float qv = cb[best * 64 + tid];
        size_t oi = ((size_t)b * LL + l) * CVQd + tid;
        __half h, lo;
        split_f16(qv, h, lo);
        qh[oi] = h; ql[oi] = lo;
        float dd = zsh[tid] - qv;
        part = dd * dd;
    }
    dsh[tid] = part;
    __syncthreads();
    for (int s = 64; s > 0; s >>= 1) { if (tid < s) dsh[tid] += dsh[tid + s]; __syncthreads(); }
    if (tid == 0) {
        atomicAdd(loss, dsh[0]);
        outIdx[b * LL + l] = (float)best;
    }
}

__global__ void loss_fin(const float* loss, float* out)
{
    out[0] = loss[0] * 0.25f / (float)(BB * LL * CVQd);
}

// ---------------- launch ----------------
extern "C" void kernel_launch(void* const* d_in, const int* in_sizes, int n_in,
                              void* d_out, int out_size)
{
    float* scratch = nullptr;
    cudaGetSymbolAddress((void**)&scratch, g_scratch);
    float*  bx  = scratch + O_BX;
    float*  by  = scratch + O_BY;
    __half* bnh = (__half*)(scratch + O_BNH);
    __half* bnl = (__half*)(scratch + O_BNL);
    __half* bmh = (__half*)(scratch + O_BMH);
    __half* bml = (__half*)(scratch + O_BML);
    __half* xh  = (__half*)(scratch + O_XH);
    __half* xl  = (__half*)(scratch + O_XL);
    __half* byh = (__half*)(scratch + O_BYH);
    __half* byl = (__half*)(scratch + O_BYL);
    float*  seg = scratch + O_SEG;
    float*  cnt = scratch + O_CNT;
    float*  bz  = scratch + O_BZ;
    __half* qh  = (__half*)(scratch + O_QH);
    __half* ql  = (__half*)(scratch + O_QL);
    float*  loss = scratch + O_LOSS;
    __half* wh  = (__half*)(scratch + O_WH);
    __half* wl  = (__half*)(scratch + O_WL);

    const float* x        = (const float*)d_in[0];
    const float* in_mask  = (const float*)d_in[1];
    const int*   mel2ph   = (const int*)  d_in[2];
    const float* ph_mask  = (const float*)d_in[3];
    const float* conv_in_w = (const float*)d_in[4];
    const float* conv_in_b = (const float*)d_in[5];
    const float* enc_ln_g = (const float*)d_in[6];
    const float* enc_ln_b = (const float*)d_in[7];
    const float* enc_w1   = (const float*)d_in[8];
    const float* enc_b1   = (const float*)d_in[9];
    const float* enc_w2   = (const float*)d_in[10];
    const float* enc_b2   = (const float*)d_in[11];
    const float* enc_last_g = (const float*)d_in[12];
    const float* enc_last_b = (const float*)d_in[13];
    const float* enc_post_w = (const float*)d_in[14];
    const float* enc_post_b = (const float*)d_in[15];
    const float* pn_ln_g = (const float*)d_in[16];
    const float* pn_ln_b = (const float*)d_in[17];
    const float* pn_w1   = (const float*)d_in[18];
    const float* pn_b1   = (const float*)d_in[19];
    const float* pn_w2   = (const float*)d_in[20];
    const float* pn_b2   = (const float*)d_in[21];
    const float* pn_last_g = (const float*)d_in[22];
    const float* pn_last_b = (const float*)d_in[23];
    const float* pn_post_w = (const float*)d_in[24];
    const float* pn_post_b = (const float*)d_in[25];
    const float* proj_in_w  = (const float*)d_in[26];
    const float* proj_in_b  = (const float*)d_in[27];
    const float* proj_out_w = (const float*)d_in[28];
    const float* proj_out_b = (const float*)d_in[29];
    const float* codebook   = (const float*)d_in[30];

    float* out = (float*)d_out;
    const float scale = 0.57735026918962576f;   // 3^-0.5

    // smem: KS=3: 4 buf * 2*(132*24 + 64*56) halves * 2B = 108032 B (2 CTAs/SM)
    //       KS=1: 4 buf * 2*(128*24 + 64*24) halves * 2B =  73728 B (2 CTAs/SM)
    const int SM3 = 4 * 2 * (132 * 24 + 64 * 56) * 2;
    const int SM1 = 4 * 2 * (128 * 24 + 64 * 24) * 2;
    cudaFuncSetAttribute(mma_conv<3>, cudaFuncAttributeMaxDynamicSharedMemorySize, SM3);
    cudaFuncSetAttribute(mma_conv<1>, cudaFuncAttributeMaxDynamicSharedMemorySize, SM1);

    dim3 blk(256);

    // ---- prepass (single launch) + early independent zero/init ----
    prep_all<<<dim3(15360, 10), 256>>>(x, conv_in_w, enc_w1, enc_w2, enc_post_w,
                                       pn_w1, pn_w2, pn_post_w, proj_in_w, proj_out_w,
                                       wh, wl, xh, xl);
    seg_zero<<<((int)SZ_SEG + 255)/256, 256>>>(seg, cnt);
    loss_init<<<1, 32>>>(loss);

    // ---- encoder (T = TT) ----
    mma_conv<1><<<dim3(TT/128, HH/64, BB), blk, SM1>>>(xh, xl, wh + OW_CIN, wl + OW_CIN,
        conv_in_b, bx, 1, nullptr, nullptr, nullptr, in_mask, CINP, HH, TT, 1.f, 0);
    for (int i = 0; i < NLB; i++) {
        ln_kernel<<<(BB*TT)/8, 256>>>(bx, bnh, bnl,
            enc_ln_g + i*HH, enc_ln_b + i*HH, nullptr, TT);
        mma_conv<3><<<dim3(TT/128, HH2/64, BB), blk, SM3>>>(bnh, bnl,
            wh + OW_E1 + (size_t)i*HH2*HH*3, wl + OW_E1 + (size_t)i*HH2*HH*3,
            enc_b1 + i*HH2, nullptr, 0, bmh, bml, nullptr, nullptr, HH, HH2, TT, scale, 1);
        mma_conv<1><<<dim3(TT/128, HH/64, BB), blk, SM1>>>(bmh, bml,
            wh + OW_E2 + (size_t)i*HH*HH2, wl + OW_E2 + (size_t)i*HH*HH2,
            enc_b2 + i*HH, bx, 1, nullptr, nullptr, bx, in_mask, HH2, HH, TT, 1.f, 0);
    }
    ln_kernel<<<(BB*TT)/8, 256>>>(bx, bnh, bnl, enc_last_g, enc_last_b, in_mask, TT);
    mma_conv<3><<<dim3(TT/128, HH/64, BB), blk, SM3>>>(bnh, bnl, wh + OW_EP, wl + OW_EP,
        enc_post_b, by, 1, nullptr, nullptr, nullptr, in_mask, HH, HH, TT, 1.f, 0);

    // ---- group by segments -> [b][l][c] into bx ----
    seg_scatter<<<dim3(TT, BB), HH>>>(by, mel2ph, seg, cnt);
    seg_div<<<(BB*LL*HH + 255)/256, 256>>>(seg, cnt, bx);

    // ---- postnet (T = LL) ----
    for (int i = 0; i < NLB; i++) {
        ln_kernel<<<(BB*LL)/8, 256>>>(bx, bnh, bnl,
            pn_ln_g + i*HH, pn_ln_b + i*HH, nullptr, LL);
        mma_conv<3><<<dim3(LL/128, HH2/64, BB), blk, SM3>>>(bnh, bnl,
            wh + OW_P1 + (size_t)i*HH2*HH*3, wl + OW_P1 + (size_t)i*HH2*HH*3,
            pn_b1 + i*HH2, nullptr, 0, bmh, bml, nullptr, nullptr, HH, HH2, LL, scale, 1);
        mma_conv<1><<<dim3(LL/128, HH/64, BB), blk, SM1>>>(bmh, bml,
            wh + OW_P2 + (size_t)i*HH*HH2, wl + OW_P2 + (size_t)i*HH*HH2,
            pn_b2 + i*HH, bx, 1, nullptr, nullptr, bx, ph_mask, HH2, HH, LL, 1.f, 0);
    }
    ln_kernel<<<(BB*LL)/8, 256>>>(bx, bnh, bnl, pn_last_g, pn_last_b, ph_mask, LL);
    mma_conv<3><<<dim3(LL/128, HH/64, BB), blk, SM3>>>(bnh, bnl, wh + OW_PP, wl + OW_PP,
        pn_post_b, nullptr, 0, byh, byl, nullptr, ph_mask, HH, HH, LL, 1.f, 0);

    // ---- proj_in -> VQ -> proj_out ----
    mma_conv<1><<<dim3(LL/128, 1, BB), blk, SM1>>>(byh, byl, wh + OW_PI, wl + OW_PI,
        proj_in_b, bz, 1, nullptr, nullptr, nullptr, nullptr, HH, CVQd, LL, 1.f, 0);
    vq_kernel<<<dim3(LL, BB), 128>>>(bz, codebook, qh, ql, out + (size_t)BB*HH*LL + 1, loss);
    mma_conv<1><<<dim3(LL/128, HH/64, BB), blk, SM1>>>(qh, ql, wh + OW_PO, wl + OW_PO,
        proj_out_b, out, 0, nullptr, nullptr, nullptr, nullptr, CVQd, HH, LL, 1.f, 0);
    loss_fin<<<1, 1>>>(loss, out + (size_t)BB*HH*LL);
}

// round 13
// speedup vs baseline: 1.0412x; 1.0412x over previous
#include <cuda_runtime.h>
#include <cuda_fp16.h>
#include <math.h>
#include <stdint.h>

// ---------------- problem constants ----------------
#define BB   16
#define TT   2048
#define LL   512
#define HH   256
#define HH2  512
#define CVQd 64
#define NLB  10   // NL * NB
#define CINP 96   // conv_in padded channels (80 -> 96)

// ---------------- sizes (floats) ----------------
#define SZ_BHT  ((size_t)BB*HH*TT)
#define SZ_BMT  ((size_t)BB*HH2*TT)
#define SZ_XP   ((size_t)BB*CINP*TT)
#define SZ_BHL  ((size_t)BB*HH*LL)
#define SZ_SEG  ((size_t)BB*HH*(LL+1))
#define SZ_CNT  ((size_t)BB*(LL+1))
#define SZ_BZL  ((size_t)BB*CVQd*LL)

// weight plane sizes (elements)
#define WSZ_CIN ((size_t)HH*CINP)
#define WSZ_E1  ((size_t)NLB*HH2*HH*3)
#define WSZ_E2  ((size_t)NLB*HH*HH2)
#define WSZ_EP  ((size_t)HH*HH*3)
#define WSZ_PI  ((size_t)CVQd*HH)
#define WSZ_PO  ((size_t)HH*CVQd)
#define WTOT    (WSZ_CIN + 2*(WSZ_E1 + WSZ_E2 + WSZ_EP) + WSZ_PI + WSZ_PO)

// scratch offsets (float units). half planes take size/2 floats.
// ALL activation tensors are t-major: [b][t][c].
#define O_BX   ((size_t)0)
#define O_BY   (O_BX  + SZ_BHT)
#define O_BNH  (O_BY  + SZ_BHT)
#define O_BNL  (O_BNH + SZ_BHT/2)
#define O_BMH  (O_BNL + SZ_BHT/2)
#define O_BML  (O_BMH + SZ_BMT/2)
#define O_XH   (O_BML + SZ_BMT/2)
#define O_XL   (O_XH  + SZ_XP/2)
#define O_BYH  (O_XL  + SZ_XP/2)
#define O_BYL  (O_BYH + SZ_BHL/2)
#define O_SEG  (O_BYL + SZ_BHL/2)
#define O_CNT  (O_SEG + SZ_SEG)
#define O_BZ   (O_CNT + SZ_CNT)
#define O_QH   (O_BZ  + SZ_BZL)
#define O_QL   (O_QH  + SZ_BZL/2)
#define O_LOSS (O_QL  + SZ_BZL/2)
#define O_WH   (O_LOSS + 16)
#define O_WL   (O_WH  + WTOT/2)
#define SCRATCH_TOT (O_WL + WTOT/2)

__device__ __align__(16) float g_scratch[SCRATCH_TOT];

// weight offsets inside wh/wl planes (element units)
#define OW_CIN ((size_t)0)
#define OW_E1  (OW_CIN + WSZ_CIN)
#define OW_E2  (OW_E1 + WSZ_E1)
#define OW_EP  (OW_E2 + WSZ_E2)
#define OW_P1  (OW_EP + WSZ_EP)
#define OW_P2  (OW_P1 + WSZ_E1)
#define OW_PP  (OW_P2 + WSZ_E2)
#define OW_PI  (OW_PP + WSZ_EP)
#define OW_PO  (OW_PI + WSZ_PI)

// ---------------- helpers ----------------
__device__ __forceinline__ uint32_t smem_to_u32(const void* p) {
    uint32_t a;
    asm("{ .reg .u64 t; cvta.to.shared.u64 t, %1; cvt.u32.u64 %0, t; }" : "=r"(a) : "l"(p));
    return a;
}
#define CP16(dst, src) \
    asm volatile("cp.async.cg.shared.global [%0], [%1], 16;" :: "r"(dst), "l"(src))
#define CP16A(dst, src) \
    asm volatile("cp.async.ca.shared.global [%0], [%1], 16;" :: "r"(dst), "l"(src))
#define CP16Z(dst, src, ssz) \
    asm volatile("cp.async.cg.shared.global [%0], [%1], 16, %2;" :: "r"(dst), "l"(src), "r"(ssz))

#define LDSM4(r0, r1, r2, r3, addr)                                              \
    asm volatile("ldmatrix.sync.aligned.m8n8.x4.shared.b16 {%0,%1,%2,%3}, [%4];" \
        : "=r"(r0), "=r"(r1), "=r"(r2), "=r"(r3) : "r"(addr))

#define MMA_F16(C, A, B)                                                         \
    asm volatile("mma.sync.aligned.m16n8k16.row.col.f32.f16.f16.f32 "            \
        "{%0,%1,%2,%3}, {%4,%5,%6,%7}, {%8,%9}, {%0,%1,%2,%3};"                  \
        : "+f"((C)[0]), "+f"((C)[1]), "+f"((C)[2]), "+f"((C)[3])                  \
        : "r"((A)[0]), "r"((A)[1]), "r"((A)[2]), "r"((A)[3]),                     \
          "r"((B)[0]), "r"((B)[1]))

__device__ __forceinline__ void split_f16(float v, __half& h, __half& l)
{
    h = __float2half_rn(v);
    l = __float2half_rn(v - __half2float(h));
}

// ---------------- merged prepass ----------------
__device__ __forceinline__ void prep_one(const float* __restrict__ w,
                                         __half* __restrict__ oh, __half* __restrict__ ol,
                                         int total, int Cout, int Cin, int KS, int idx)
{
    if (idx >= total) return;
    int per_layer = Cout * Cin * KS;
    int layer = idx / per_layer;
    int r = idx - layer * per_layer;
    int co = r / (Cin * KS);
    int r2 = r - co * (Cin * KS);
    int ci = r2 / KS;
    int tap = r2 - ci * KS;
    __half h, l;
    split_f16(w[idx], h, l);
    int kidx = (ci >> 4) * (16 * KS) + tap * 16 + (ci & 15);
    size_t o = ((size_t)layer * Cout + co) * (size_t)(Cin * KS) + kidx;
    oh[o] = h; ol[o] = l;
}

__global__ void prep_all(
    const float* __restrict__ x,
    const float* __restrict__ cinw, const float* __restrict__ e1,
    const float* __restrict__ e2,  const float* __restrict__ ep,
    const float* __restrict__ p1,  const float* __restrict__ p2,
    const float* __restrict__ pp,  const float* __restrict__ pi,
    const float* __restrict__ po,
    __half* __restrict__ wh, __half* __restrict__ wl,
    __half* __restrict__ xh, __half* __restrict__ xl)
{
    int idx = blockIdx.x * 256 + threadIdx.x;
    switch (blockIdx.y) {
    case 0:  // conv_in weights padded 80 -> 96 ci (KS=1, kidx = ci)
        if (idx < (int)WSZ_CIN) {
            int co = idx / CINP, ci = idx - co * CINP;
            float v = (ci < 80) ? cinw[co * 80 + ci] : 0.f;
            __half h, l;
            split_f16(v, h, l);
            wh[OW_CIN + idx] = h; wl[OW_CIN + idx] = l;
        }
        break;
    case 1: prep_one(e1, wh + OW_E1, wl + OW_E1, (int)WSZ_E1, HH2, HH, 3, idx); break;
    case 2: prep_one(e2, wh + OW_E2, wl + OW_E2, (int)WSZ_E2, HH, HH2, 1, idx); break;
    case 3: prep_one(ep, wh + OW_EP, wl + OW_EP, (int)WSZ_EP, HH, HH, 3, idx); break;
    case 4: prep_one(p1, wh + OW_P1, wl + OW_P1, (int)WSZ_E1, HH2, HH, 3, idx); break;
    case 5: prep_one(p2, wh + OW_P2, wl + OW_P2, (int)WSZ_E2, HH, HH2, 1, idx); break;
    case 6: prep_one(pp, wh + OW_PP, wl + OW_PP, (int)WSZ_EP, HH, HH, 3, idx); break;
    case 7: prep_one(pi, wh + OW_PI, wl + OW_PI, (int)WSZ_PI, CVQd, HH, 1, idx); break;
    case 8: prep_one(po, wh + OW_PO, wl + OW_PO, (int)WSZ_PO, HH, CVQd, 1, idx); break;
    default:  // x -> 96-channel t-major planes (zero-padded)
        if (idx < (int)SZ_XP) {
            int b = idx / (CINP * TT);
            int r = idx - b * CINP * TT;
            int t = r / CINP, c = r - t * CINP;
            float v = (c < 80) ? x[((size_t)b * 80 + c) * TT + t] : 0.f;
            __half h, l;
            split_f16(v, h, l);
            size_t o = ((size_t)b * TT + t) * CINP + c;
            xh[o] = h; xl[o] = l;
        }
        break;
    }
}

// ---------------- LayerNorm (t-major): warp per row ----------------
__global__ void ln_kernel(const float* __restrict__ in, __half* __restrict__ outh,
                          __half* __restrict__ outl,
                          const float* __restrict__ gma, const float* __restrict__ bta,
                          const float* __restrict__ mask, int Tdim)
{
    int row = blockIdx.x * 8 + (threadIdx.x >> 5);
    if (row >= BB * Tdim) return;
    int lane = threadIdx.x & 31;
    const float4* p = (const float4*)(in + (size_t)row * HH) + lane * 2;
    float4 a = p[0], q = p[1];
    float v[8] = {a.x, a.y, a.z, a.w, q.x, q.y, q.z, q.w};
    float s = 0.f, s2 = 0.f;
    #pragma unroll
    for (int i = 0; i < 8; i++) { s += v[i]; s2 += v[i] * v[i]; }
    #pragma unroll
    for (int o = 16; o; o >>= 1) {
        s  += __shfl_xor_sync(0xffffffffu, s, o);
        s2 += __shfl_xor_sync(0xffffffffu, s2, o);
    }
    float mean = s * (1.f / HH);
    float var  = s2 * (1.f / HH) - mean * mean;
    float r = rsqrtf(var + 1e-5f);
    float mk = mask ? mask[row] : 1.f;
    __half2 hv[4], lv[4];
    #pragma unroll
    for (int i = 0; i < 4; i++) {
        int c = lane * 8 + 2 * i;
        float n0 = ((v[2*i]   - mean) * r * gma[c]     + bta[c])     * mk;
        float n1 = ((v[2*i+1] - mean) * r * gma[c + 1] + bta[c + 1]) * mk;
        __half h0, l0, h1, l1;
        split_f16(n0, h0, l0);
        split_f16(n1, h1, l1);
        hv[i] = __halves2half2(h0, h1);
        lv[i] = __halves2half2(l0, l1);
    }
    *(uint4*)(outh + (size_t)row * HH + lane * 8) = *(uint4*)hv;
    *(uint4*)(outl + (size_t)row * HH + lane * 8) = *(uint4*)lv;
}

// ---------------- fp16-split mma.sync conv GEMM ----------------
// KS=3: 4-buffer pipeline (prefetch distance 3, wait_group 2), stage = 16 ci,
//       X un-replicated 130 rows x 16ci (48B rows); taps = ldmatrix row shifts.
// KS=1: 3-buffer pipeline (distance 2, wait_group 1), stage = 32 ci, 80B rows.
template<int KS>
__global__ void __launch_bounds__(256, 2)
mma_conv(const __half* __restrict__ inh, const __half* __restrict__ inl,
         const __half* __restrict__ wh, const __half* __restrict__ wl,
         const float* __restrict__ bias,
         float* outF, int tmaj, __half* outH, __half* outL,
         const float* __restrict__ residual, const float* __restrict__ mask,
         int Cin, int Cout, int Tdim, float scale, int dogelu)
{
    extern __shared__ char smc[];
    constexpr int SXX = (KS == 3) ? 24 : 40;       // X row stride (halves); bytes mult of 16
    constexpr int SXW = (KS == 3) ? 56 : 40;       // W row stride (halves)
    constexpr int XPL = (KS == 3) ? 132 * 24 : 128 * 40;
    constexpr int WPL = 64 * SXW;
    constexpr int BUF = 2 * (XPL + WPL);
    constexpr int NBUF = (KS == 3) ? 4 : 3;

    const int b   = blockIdx.z;
    const int cog = blockIdx.y * 64;
    const int tg  = blockIdx.x * 128;
    const int tid = threadIdx.x;
    const int lane = tid & 31, wid = tid >> 5;
    const int wm = wid >> 2, wn = wid & 3;
    const int g = lane >> 2, th = lane & 3;

    const uint32_t smb = smem_to_u32(smc);
    const int Ktot = Cin * KS;
    const size_t xb = (size_t)b * Tdim * Cin;   // half units

    const int laneA = ((lane & 7) + ((lane >> 3) & 1) * 8) * SXW + (lane >> 4) * 8;
    const int laneB = ((lane & 7) + (lane >> 4) * 8) * SXX + ((lane >> 3) & 1) * 8;

    float c[2][4][4];
    #pragma unroll
    for (int i = 0; i < 2; i++)
        #pragma unroll
        for (int j = 0; j < 4; j++)
            #pragma unroll
            for (int k = 0; k < 4; k++) c[i][j][k] = 0.f;

    const int nst = (KS == 3) ? (Cin >> 4) : (Cin >> 5);

    auto load_stage = [&](int s, int buf) {
        const uint32_t bb = smb + 2u * (uint32_t)(buf * BUF);
        if (KS == 3) {
            const int ci0 = s * 16;
            // W: 2 planes x 64 rows x 6 chunks = 768 (L1-cached: shared across CTAs)
            #pragma unroll
            for (int it = 0; it < 3; it++) {
                int ic = it * 256 + tid;
                int plane = (ic >= 384) ? 1 : 0;
                int r = ic - plane * 384;
                int row = r / 6, ch = r - row * 6;
                const __half* src = (plane ? wl : wh) + (size_t)(cog + row) * Ktot + s * 48 + ch * 8;
                CP16A(bb + 2u * (uint32_t)(2 * XPL + plane * WPL + row * SXW + ch * 8), src);
            }
            // X: 2 planes x 130 rows x 2 chunks = 520
            #pragma unroll
            for (int it = 0; it < 3; it++) {
                int ic = it * 256 + tid;
                if (ic < 520) {
                    int plane = (ic >= 260) ? 1 : 0;
                    int r = ic - plane * 260;
                    int u = r >> 1, ch = r & 1;
                    int gt = tg - 2 + u;
                    const __half* src = (plane ? inl : inh) + xb + (size_t)gt * Cin + ci0 + ch * 8;
                    int ssz = (gt >= 0) ? 16 : 0;
                    CP16Z(bb + 2u * (uint32_t)(plane * XPL + u * SXX + ch * 8), src, ssz);
                }
            }
        } else {
            const int ci0 = s * 32;
            // W: 2 planes x 64 rows x 4 chunks = 512 (L1-cached)
            #pragma unroll
            for (int it = 0; it < 2; it++) {
                int ic = it * 256 + tid;
                int plane = ic >> 8, r = ic & 255;
                int row = r >> 2, ch = r & 3;
                const __half* src = (plane ? wl : wh) + (size_t)(cog + row) * Ktot + ci0 + ch * 8;
                CP16A(bb + 2u * (uint32_t)(2 * XPL + plane * WPL + row * SXW + ch * 8), src);
            }
            // X: 2 planes x 128 rows x 4 chunks = 1024
            #pragma unroll
            for (int it = 0; it < 4; it++) {
                int ic = it * 256 + tid;
                int plane = ic >> 9, r = ic & 511;
                int t = r >> 2, ch = r & 3;
                const __half* src = (plane ? inl : inh) + xb + (size_t)(tg + t) * Cin + ci0 + ch * 8;
                CP16(bb + 2u * (uint32_t)(plane * XPL + t * SXX + ch * 8), src);
            }
        }
    };

    auto compute = [&](int buf) {
        const uint32_t bb = smb + 2u * (uint32_t)(buf * BUF);
        constexpr int KST = (KS == 3) ? 3 : 2;
        #pragma unroll
        for (int ks = 0; ks < KST; ks++) {
            uint32_t ah[2][4], al[2][4], bh[4][2], bl[4][2];
            #pragma unroll
            for (int mf = 0; mf < 2; mf++) {
                uint32_t base = bb + 2u * (uint32_t)(2 * XPL + (wm * 32 + mf * 16) * SXW + ks * 16 + laneA);
                LDSM4(ah[mf][0], ah[mf][1], ah[mf][2], ah[mf][3], base);
                LDSM4(al[mf][0], al[mf][1], al[mf][2], al[mf][3], base + 2u * (uint32_t)WPL);
            }
            #pragma unroll
            for (int p = 0; p < 2; p++) {
                int rowb = wn * 32 + p * 16 + ((KS == 3) ? ks : 0);
                int colb = (KS == 3) ? 0 : ks * 16;
                uint32_t base = bb + 2u * (uint32_t)(rowb * SXX + colb + laneB);
                LDSM4(bh[2*p][0], bh[2*p][1], bh[2*p+1][0], bh[2*p+1][1], base);
                LDSM4(bl[2*p][0], bl[2*p][1], bl[2*p+1][0], bl[2*p+1][1], base + 2u * (uint32_t)XPL);
            }
            #pragma unroll
            for (int mf = 0; mf < 2; mf++)
                #pragma unroll
                for (int nf = 0; nf < 4; nf++) {
                    MMA_F16(c[mf][nf], ah[mf], bh[nf]);
                    MMA_F16(c[mf][nf], ah[mf], bl[nf]);
                    MMA_F16(c[mf][nf], al[mf], bh[nf]);
                }
        }
    };

    // ---- pipelined mainloop (prefetch distance NBUF-1) ----
    {
        int pre = (nst < NBUF - 1) ? nst : (NBUF - 1);
        for (int p = 0; p < pre; p++) {
            load_stage(p, p);
            asm volatile("cp.async.commit_group;");
        }
    }
    for (int s = 0; s < nst; s++) {
        if (KS == 3) {
            if (s + 2 < nst)      asm volatile("cp.async.wait_group 2;");
            else if (s + 1 < nst) asm volatile("cp.async.wait_group 1;");
            else                  asm volatile("cp.async.wait_group 0;");
        } else {
            if (s + 1 < nst)      asm volatile("cp.async.wait_group 1;");
            else                  asm volatile("cp.async.wait_group 0;");
        }
        __syncthreads();
        if (s + NBUF - 1 < nst) {
            load_stage(s + NBUF - 1, (s + NBUF - 1) % NBUF);
            asm volatile("cp.async.commit_group;");
        }
        compute(s % NBUF);
    }

    // ---- epilogue ----
    #pragma unroll
    for (int mf = 0; mf < 2; mf++) {
        #pragma unroll
        for (int nf = 0; nf < 4; nf++) {
            int co0 = cog + wm * 32 + mf * 16 + g;
            int t0 = tg + wn * 32 + nf * 8 + 2 * th;
            float mk0 = mask ? mask[b * Tdim + t0] : 1.f;
            float mk1 = mask ? mask[b * Tdim + t0 + 1] : 1.f;
            #pragma unroll
            for (int half = 0; half < 2; half++) {
                int co = co0 + half * 8;
                float bi = bias[co];
                float v0 = (c[mf][nf][half * 2 + 0] + bi) * scale;
                float v1 = (c[mf][nf][half * 2 + 1] + bi) * scale;
                if (dogelu) {
                    v0 = 0.5f * v0 * (1.f + erff(v0 * 0.70710678118654752f));
                    v1 = 0.5f * v1 * (1.f + erff(v1 * 0.70710678118654752f));
                }
                size_t r0 = ((size_t)b * Tdim + t0) * Cout + co;
                size_t r1 = r0 + Cout;
                if (residual) { v0 += residual[r0]; v1 += residual[r1]; }
                if (mask) { v0 *= mk0; v1 *= mk1; }
                if (outF) {
                    if (tmaj) { outF[r0] = v0; outF[r1] = v1; }
                    else {
                        size_t o = ((size_t)b * Cout + co) * Tdim + t0;
                        outF[o] = v0; outF[o + 1] = v1;
                    }
                }
                if (outH) {
                    __half h0, l0, h1, l1;
                    split_f16(v0, h0, l0);
                    split_f16(v1, h1, l1);
                    outH[r0] = h0; outH[r1] = h1;
                    outL[r0] = l0; outL[r1] = l1;
                }
            }
        }
    }
}

// ---------------- group_by_segs (t-major) ----------------
__global__ void seg_zero(float* seg, float* cnt)
{
    int i = blockIdx.x * blockDim.x + threadIdx.x;
    if (i < (int)SZ_SEG) seg[i] = 0.f;
    if (i < (int)SZ_CNT) cnt[i] = 0.f;
}
__global__ void seg_scatter(const float* __restrict__ in, const int* __restrict__ mel2ph,
                            float* seg, float* cnt)
{
    int t = blockIdx.x, b = blockIdx.y, c = threadIdx.x;
    int ph = mel2ph[b * TT + t];
    if (ph < 1 || ph > LL) return;
    float v = in[((size_t)b * TT + t) * HH + c];
    atomicAdd(&seg[((size_t)b * (LL + 1) + ph) * HH + c], v);
    if (c == 0) atomicAdd(&cnt[b * (LL + 1) + ph], 1.f);
}
__global__ void seg_div(const float* __restrict__ seg, const float* __restrict__ cnt,
                        float* __restrict__ outg)
{
    int i = blockIdx.x * blockDim.x + threadIdx.x;   // over [b][l][c]
    if (i >= BB * LL * HH) return;
    int c = i % HH; int bl = i / HH; int l = bl % LL; int b = bl / LL;
    float s = seg[((size_t)b * (LL + 1) + l + 1) * HH + c];
    float n = fmaxf(cnt[b * (LL + 1) + l + 1], 1.f);
    outg[i] = s / n;
}

// ---------------- VQ (t-major) ----------------
__global__ void loss_init(float* loss) { if (threadIdx.x == 0) *loss = 0.f; }

__global__ void vq_kernel(const float* __restrict__ z, const float* __restrict__ cb,
                          __half* __restrict__ qh, __half* __restrict__ ql,
                          float* __restrict__ outIdx, float* loss)
{
    __shared__ float zsh[64];
    __shared__ float dsh[128];
    __shared__ int   ish[128];
    int l = blockIdx.x, b = blockIdx.y, tid = threadIdx.x;
    if (tid < 64) zsh[tid] = z[((size_t)b * LL + l) * CVQd + tid];
    __syncthreads();
    float x2 = 0.f, dot = 0.f, c2 = 0.f;
    #pragma unroll 8
    for (int c = 0; c < 64; c++) {
        float zv = zsh[c]; float cv = cb[tid * 64 + c];
        x2 += zv * zv; dot += zv * cv; c2 += cv * cv;
    }
    dsh[tid] = x2 - 2.f * dot + c2;
    ish[tid] = tid;
    __syncthreads();
    for (int s = 64; s > 0; s >>= 1) {
        if (tid < s) {
            float d2 = dsh[tid + s]; int i2 = ish[tid + s];
            if (d2 < dsh[tid] || (d2 == dsh[tid] && i2 < ish[tid])) { dsh[tid] = d2; ish[tid] = i2; }
        }
        __syncthreads();
    }
    int best = ish[0];
    __syncthreads();
    float part = 0.f;
    if (tid < 64) {
        float qv = cb[best * 64 + tid];
        size_t oi = ((size_t)b * LL + l) * CVQd + tid;
        __half h, lo;
        split_f16(qv, h, lo);
        qh[oi] = h; ql[oi] = lo;
        float dd = zsh[tid] - qv;
        part = dd * dd;
    }
    dsh[tid] = part;
    __syncthreads();
    for (int s = 64; s > 0; s >>= 1) { if (tid < s) dsh[tid] += dsh[tid + s]; __syncthreads(); }
    if (tid == 0) {
        atomicAdd(loss, dsh[0]);
        outIdx[b * LL + l] = (float)best;
    }
}

__global__ void loss_fin(const float* loss, float* out)
{
    out[0] = loss[0] * 0.25f / (float)(BB * LL * CVQd);
}

// ---------------- launch ----------------
extern "C" void kernel_launch(void* const* d_in, const int* in_sizes, int n_in,
                              void* d_out, int out_size)
{
    float* scratch = nullptr;
    cudaGetSymbolAddress((void**)&scratch, g_scratch);
    float*  bx  = scratch + O_BX;
    float*  by  = scratch + O_BY;
    __half* bnh = (__half*)(scratch + O_BNH);
    __half* bnl = (__half*)(scratch + O_BNL);
    __half* bmh = (__half*)(scratch + O_BMH);
    __half* bml = (__half*)(scratch + O_BML);
    __half* xh  = (__half*)(scratch + O_XH);
    __half* xl  = (__half*)(scratch + O_XL);
    __half* byh = (__half*)(scratch + O_BYH);
    __half* byl = (__half*)(scratch + O_BYL);
    float*  seg = scratch + O_SEG;
    float*  cnt = scratch + O_CNT;
    float*  bz  = scratch + O_BZ;
    __half* qh  = (__half*)(scratch + O_QH);
    __half* ql  = (__half*)(scratch + O_QL);
    float*  loss = scratch + O_LOSS;
    __half* wh  = (__half*)(scratch + O_WH);
    __half* wl  = (__half*)(scratch + O_WL);

    const float* x        = (const float*)d_in[0];
    const float* in_mask  = (const float*)d_in[1];
    const int*   mel2ph   = (const int*)  d_in[2];
    const float* ph_mask  = (const float*)d_in[3];
    const float* conv_in_w = (const float*)d_in[4];
    const float* conv_in_b = (const float*)d_in[5];
    const float* enc_ln_g = (const float*)d_in[6];
    const float* enc_ln_b = (const float*)d_in[7];
    const float* enc_w1   = (const float*)d_in[8];
    const float* enc_b1   = (const float*)d_in[9];
    const float* enc_w2   = (const float*)d_in[10];
    const float* enc_b2   = (const float*)d_in[11];
    const float* enc_last_g = (const float*)d_in[12];
    const float* enc_last_b = (const float*)d_in[13];
    const float* enc_post_w = (const float*)d_in[14];
    const float* enc_post_b = (const float*)d_in[15];
    const float* pn_ln_g = (const float*)d_in[16];
    const float* pn_ln_b = (const float*)d_in[17];
    const float* pn_w1   = (const float*)d_in[18];
    const float* pn_b1   = (const float*)d_in[19];
    const float* pn_w2   = (const float*)d_in[20];
    const float* pn_b2   = (const float*)d_in[21];
    const float* pn_last_g = (const float*)d_in[22];
    const float* pn_last_b = (const float*)d_in[23];
    const float* pn_post_w = (const float*)d_in[24];
    const float* pn_post_b = (const float*)d_in[25];
    const float* proj_in_w  = (const float*)d_in[26];
    const float* proj_in_b  = (const float*)d_in[27];
    const float* proj_out_w = (const float*)d_in[28];
    const float* proj_out_b = (const float*)d_in[29];
    const float* codebook   = (const float*)d_in[30];

    float* out = (float*)d_out;
    const float scale = 0.57735026918962576f;   // 3^-0.5

    // smem: KS=3: 4 buf * 2*(132*24 + 64*56) halves * 2B = 108032 B (2 CTAs/SM)
    //       KS=1: 3 buf * 2*(128*40 + 64*40) halves * 2B =  92160 B (2 CTAs/SM)
    const int SM3 = 4 * 2 * (132 * 24 + 64 * 56) * 2;
    const int SM1 = 3 * 2 * (128 * 40 + 64 * 40) * 2;
    cudaFuncSetAttribute(mma_conv<3>, cudaFuncAttributeMaxDynamicSharedMemorySize, SM3);
    cudaFuncSetAttribute(mma_conv<1>, cudaFuncAttributeMaxDynamicSharedMemorySize, SM1);

    dim3 blk(256);

    // ---- prepass (single launch) + early independent zero/init ----
    prep_all<<<dim3(15360, 10), 256>>>(x, conv_in_w, enc_w1, enc_w2, enc_post_w,
                                       pn_w1, pn_w2, pn_post_w, proj_in_w, proj_out_w,
                                       wh, wl, xh, xl);
    seg_zero<<<((int)SZ_SEG + 255)/256, 256>>>(seg, cnt);
    loss_init<<<1, 32>>>(loss);

    // ---- encoder (T = TT) ----
    mma_conv<1><<<dim3(TT/128, HH/64, BB), blk, SM1>>>(xh, xl, wh + OW_CIN, wl + OW_CIN,
        conv_in_b, bx, 1, nullptr, nullptr, nullptr, in_mask, CINP, HH, TT, 1.f, 0);
    for (int i = 0; i < NLB; i++) {
        ln_kernel<<<(BB*TT)/8, 256>>>(bx, bnh, bnl,
            enc_ln_g + i*HH, enc_ln_b + i*HH, nullptr, TT);
        mma_conv<3><<<dim3(TT/128, HH2/64, BB), blk, SM3>>>(bnh, bnl,
            wh + OW_E1 + (size_t)i*HH2*HH*3, wl + OW_E1 + (size_t)i*HH2*HH*3,
            enc_b1 + i*HH2, nullptr, 0, bmh, bml, nullptr, nullptr, HH, HH2, TT, scale, 1);
        mma_conv<1><<<dim3(TT/128, HH/64, BB), blk, SM1>>>(bmh, bml,
            wh + OW_E2 + (size_t)i*HH*HH2, wl + OW_E2 + (size_t)i*HH*HH2,
            enc_b2 + i*HH, bx, 1, nullptr, nullptr, bx, in_mask, HH2, HH, TT, 1.f, 0);
    }
    ln_kernel<<<(BB*TT)/8, 256>>>(bx, bnh, bnl, enc_last_g, enc_last_b, in_mask, TT);
    mma_conv<3><<<dim3(TT/128, HH/64, BB), blk, SM3>>>(bnh, bnl, wh + OW_EP, wl + OW_EP,
        enc_post_b, by, 1, nullptr, nullptr, nullptr, in_mask, HH, HH, TT, 1.f, 0);

    // ---- group by segments -> [b][l][c] into bx ----
    seg_scatter<<<dim3(TT, BB), HH>>>(by, mel2ph, seg, cnt);
    seg_div<<<(BB*LL*HH + 255)/256, 256>>>(seg, cnt, bx);

    // ---- postnet (T = LL) ----
    for (int i = 0; i < NLB; i++) {
        ln_kernel<<<(BB*LL)/8, 256>>>(bx, bnh, bnl,
            pn_ln_g + i*HH, pn_ln_b + i*HH, nullptr, LL);
        mma_conv<3><<<dim3(LL/128, HH2/64, BB), blk, SM3>>>(bnh, bnl,
            wh + OW_P1 + (size_t)i*HH2*HH*3, wl + OW_P1 + (size_t)i*HH2*HH*3,
            pn_b1 + i*HH2, nullptr, 0, bmh, bml, nullptr, nullptr, HH, HH2, LL, scale, 1);
        mma_conv<1><<<dim3(LL/128, HH/64, BB), blk, SM1>>>(bmh, bml,
            wh + OW_P2 + (size_t)i*HH*HH2, wl + OW_P2 + (size_t)i*HH*HH2,
            pn_b2 + i*HH, bx, 1, nullptr, nullptr, bx, ph_mask, HH2, HH, LL, 1.f, 0);
    }
    ln_kernel<<<(BB*LL)/8, 256>>>(bx, bnh, bnl, pn_last_g, pn_last_b, ph_mask, LL);
    mma_conv<3><<<dim3(LL/128, HH/64, BB), blk, SM3>>>(bnh, bnl, wh + OW_PP, wl + OW_PP,
        pn_post_b, nullptr, 0, byh, byl, nullptr, ph_mask, HH, HH, LL, 1.f, 0);

    // ---- proj_in -> VQ -> proj_out ----
    mma_conv<1><<<dim3(LL/128, 1, BB), blk, SM1>>>(byh, byl, wh + OW_PI, wl + OW_PI,
        proj_in_b, bz, 1, nullptr, nullptr, nullptr, nullptr, HH, CVQd, LL, 1.f, 0);
    vq_kernel<<<dim3(LL, BB), 128>>>(bz, codebook, qh, ql, out + (size_t)BB*HH*LL + 1, loss);
    mma_conv<1><<<dim3(LL/128, HH/64, BB), blk, SM1>>>(qh, ql, wh + OW_PO, wl + OW_PO,
        proj_out_b, out, 0, nullptr, nullptr, nullptr, nullptr, CVQd, HH, LL, 1.f, 0);
    loss_fin<<<1, 1>>>(loss, out + (size_t)BB*HH*LL);
}

// round 14
// speedup vs baseline: 1.1422x; 1.0970x over previous
#include <cuda_runtime.h>
#include <cuda_fp16.h>
#include <math.h>
#include <stdint.h>

// ---------------- problem constants ----------------
#define BB   16
#define TT   2048
#define LL   512
#define HH   256
#define HH2  512
#define CVQd 64
#define NLB  10   // NL * NB
#define CINP 96   // conv_in padded channels (80 -> 96)

// ---------------- sizes (floats) ----------------
#define SZ_BHT  ((size_t)BB*HH*TT)
#define SZ_BMT  ((size_t)BB*HH2*TT)
#define SZ_XP   ((size_t)BB*CINP*TT)
#define SZ_BHL  ((size_t)BB*HH*LL)
#define SZ_SEG  ((size_t)BB*HH*(LL+1))
#define SZ_CNT  ((size_t)BB*(LL+1))
#define SZ_BZL  ((size_t)BB*CVQd*LL)

// weight plane sizes (elements)
#define WSZ_CIN ((size_t)HH*CINP)
#define WSZ_E1  ((size_t)NLB*HH2*HH*3)
#define WSZ_E2  ((size_t)NLB*HH*HH2)
#define WSZ_EP  ((size_t)HH*HH*3)
#define WSZ_PI  ((size_t)CVQd*HH)
#define WSZ_PO  ((size_t)HH*CVQd)
#define WTOT    (WSZ_CIN + 2*(WSZ_E1 + WSZ_E2 + WSZ_EP) + WSZ_PI + WSZ_PO)

// scratch offsets (float units). half planes take size/2 floats.
// ALL activation tensors are t-major: [b][t][c].
#define O_BX   ((size_t)0)
#define O_BY   (O_BX  + SZ_BHT)
#define O_BNH  (O_BY  + SZ_BHT)
#define O_BNL  (O_BNH + SZ_BHT/2)
#define O_BMH  (O_BNL + SZ_BHT/2)
#define O_BML  (O_BMH + SZ_BMT/2)
#define O_XH   (O_BML + SZ_BMT/2)
#define O_XL   (O_XH  + SZ_XP/2)
#define O_BYH  (O_XL  + SZ_XP/2)
#define O_BYL  (O_BYH + SZ_BHL/2)
#define O_SEG  (O_BYL + SZ_BHL/2)
#define O_CNT  (O_SEG + SZ_SEG)
#define O_BZ   (O_CNT + SZ_CNT)
#define O_QH   (O_BZ  + SZ_BZL)
#define O_QL   (O_QH  + SZ_BZL/2)
#define O_LOSS (O_QL  + SZ_BZL/2)
#define O_WH   (O_LOSS + 16)
#define O_WL   (O_WH  + WTOT/2)
#define SCRATCH_TOT (O_WL + WTOT/2)

__device__ __align__(16) float g_scratch[SCRATCH_TOT];

// weight offsets inside wh/wl planes (element units)
#define OW_CIN ((size_t)0)
#define OW_E1  (OW_CIN + WSZ_CIN)
#define OW_E2  (OW_E1 + WSZ_E1)
#define OW_EP  (OW_E2 + WSZ_E2)
#define OW_P1  (OW_EP + WSZ_EP)
#define OW_P2  (OW_P1 + WSZ_E1)
#define OW_PP  (OW_P2 + WSZ_E2)
#define OW_PI  (OW_PP + WSZ_EP)
#define OW_PO  (OW_PI + WSZ_PI)

// ---------------- helpers ----------------
__device__ __forceinline__ uint32_t smem_to_u32(const void* p) {
    uint32_t a;
    asm("{ .reg .u64 t; cvta.to.shared.u64 t, %1; cvt.u32.u64 %0, t; }" : "=r"(a) : "l"(p));
    return a;
}
#define CP16(dst, src) \
    asm volatile("cp.async.cg.shared.global [%0], [%1], 16;" :: "r"(dst), "l"(src))
#define CP16A(dst, src) \
    asm volatile("cp.async.ca.shared.global [%0], [%1], 16;" :: "r"(dst), "l"(src))
#define CP16Z(dst, src, ssz) \
    asm volatile("cp.async.cg.shared.global [%0], [%1], 16, %2;" :: "r"(dst), "l"(src), "r"(ssz))

#define LDSM4(r0, r1, r2, r3, addr)                                              \
    asm volatile("ldmatrix.sync.aligned.m8n8.x4.shared.b16 {%0,%1,%2,%3}, [%4];" \
        : "=r"(r0), "=r"(r1), "=r"(r2), "=r"(r3) : "r"(addr))

#define MMA_F16(C, A, B)                                                         \
    asm volatile("mma.sync.aligned.m16n8k16.row.col.f32.f16.f16.f32 "            \
        "{%0,%1,%2,%3}, {%4,%5,%6,%7}, {%8,%9}, {%0,%1,%2,%3};"                  \
        : "+f"((C)[0]), "+f"((C)[1]), "+f"((C)[2]), "+f"((C)[3])                  \
        : "r"((A)[0]), "r"((A)[1]), "r"((A)[2]), "r"((A)[3]),                     \
          "r"((B)[0]), "r"((B)[1]))

__device__ __forceinline__ void split_f16(float v, __half& h, __half& l)
{
    h = __float2half_rn(v);
    l = __float2half_rn(v - __half2float(h));
}

// ---------------- merged prepass ----------------
__device__ __forceinline__ void prep_one(const float* __restrict__ w,
                                         __half* __restrict__ oh, __half* __restrict__ ol,
                                         int total, int Cout, int Cin, int KS, int idx)
{
    if (idx >= total) return;
    int per_layer = Cout * Cin * KS;
    int layer = idx / per_layer;
    int r = idx - layer * per_layer;
    int co = r / (Cin * KS);
    int r2 = r - co * (Cin * KS);
    int ci = r2 / KS;
    int tap = r2 - ci * KS;
    __half h, l;
    split_f16(w[idx], h, l);
    int kidx = (ci >> 4) * (16 * KS) + tap * 16 + (ci & 15);
    size_t o = ((size_t)layer * Cout + co) * (size_t)(Cin * KS) + kidx;
    oh[o] = h; ol[o] = l;
}

__global__ void prep_all(
    const float* __restrict__ x,
    const float* __restrict__ cinw, const float* __restrict__ e1,
    const float* __restrict__ e2,  const float* __restrict__ ep,
    const float* __restrict__ p1,  const float* __restrict__ p2,
    const float* __restrict__ pp,  const float* __restrict__ pi,
    const float* __restrict__ po,
    __half* __restrict__ wh, __half* __restrict__ wl,
    __half* __restrict__ xh, __half* __restrict__ xl)
{
    int idx = blockIdx.x * 256 + threadIdx.x;
    switch (blockIdx.y) {
    case 0:  // conv_in weights padded 80 -> 96 ci (KS=1, kidx = ci)
        if (idx < (int)WSZ_CIN) {
            int co = idx / CINP, ci = idx - co * CINP;
            float v = (ci < 80) ? cinw[co * 80 + ci] : 0.f;
            __half h, l;
            split_f16(v, h, l);
            wh[OW_CIN + idx] = h; wl[OW_CIN + idx] = l;
        }
        break;
    case 1: prep_one(e1, wh + OW_E1, wl + OW_E1, (int)WSZ_E1, HH2, HH, 3, idx); break;
    case 2: prep_one(e2, wh + OW_E2, wl + OW_E2, (int)WSZ_E2, HH, HH2, 1, idx); break;
    case 3: prep_one(ep, wh + OW_EP, wl + OW_EP, (int)WSZ_EP, HH, HH, 3, idx); break;
    case 4: prep_one(p1, wh + OW_P1, wl + OW_P1, (int)WSZ_E1, HH2, HH, 3, idx); break;
    case 5: prep_one(p2, wh + OW_P2, wl + OW_P2, (int)WSZ_E2, HH, HH2, 1, idx); break;
    case 6: prep_one(pp, wh + OW_PP, wl + OW_PP, (int)WSZ_EP, HH, HH, 3, idx); break;
    case 7: prep_one(pi, wh + OW_PI, wl + OW_PI, (int)WSZ_PI, CVQd, HH, 1, idx); break;
    case 8: prep_one(po, wh + OW_PO, wl + OW_PO, (int)WSZ_PO, HH, CVQd, 1, idx); break;
    default:  // x -> 96-channel t-major planes (zero-padded)
        if (idx < (int)SZ_XP) {
            int b = idx / (CINP * TT);
            int r = idx - b * CINP * TT;
            int t = r / CINP, c = r - t * CINP;
            float v = (c < 80) ? x[((size_t)b * 80 + c) * TT + t] : 0.f;
            __half h, l;
            split_f16(v, h, l);
            size_t o = ((size_t)b * TT + t) * CINP + c;
            xh[o] = h; xl[o] = l;
        }
        break;
    }
}

// ---------------- LayerNorm (t-major): warp per row ----------------
__global__ void ln_kernel(const float* __restrict__ in, __half* __restrict__ outh,
                          __half* __restrict__ outl,
                          const float* __restrict__ gma, const float* __restrict__ bta,
                          const float* __restrict__ mask, int Tdim)
{
    int row = blockIdx.x * 8 + (threadIdx.x >> 5);
    if (row >= BB * Tdim) return;
    int lane = threadIdx.x & 31;
    const float4* p = (const float4*)(in + (size_t)row * HH) + lane * 2;
    float4 a = p[0], q = p[1];
    float v[8] = {a.x, a.y, a.z, a.w, q.x, q.y, q.z, q.w};
    float s = 0.f, s2 = 0.f;
    #pragma unroll
    for (int i = 0; i < 8; i++) { s += v[i]; s2 += v[i] * v[i]; }
    #pragma unroll
    for (int o = 16; o; o >>= 1) {
        s  += __shfl_xor_sync(0xffffffffu, s, o);
        s2 += __shfl_xor_sync(0xffffffffu, s2, o);
    }
    float mean = s * (1.f / HH);
    float var  = s2 * (1.f / HH) - mean * mean;
    float r = rsqrtf(var + 1e-5f);
    float mk = mask ? mask[row] : 1.f;
    __half2 hv[4], lv[4];
    #pragma unroll
    for (int i = 0; i < 4; i++) {
        int c = lane * 8 + 2 * i;
        float n0 = ((v[2*i]   - mean) * r * gma[c]     + bta[c])     * mk;
        float n1 = ((v[2*i+1] - mean) * r * gma[c + 1] + bta[c + 1]) * mk;
        __half h0, l0, h1, l1;
        split_f16(n0, h0, l0);
        split_f16(n1, h1, l1);
        hv[i] = __halves2half2(h0, h1);
        lv[i] = __halves2half2(l0, l1);
    }
    *(uint4*)(outh + (size_t)row * HH + lane * 8) = *(uint4*)hv;
    *(uint4*)(outl + (size_t)row * HH + lane * 8) = *(uint4*)lv;
}

// ---------------- fp16-split mma.sync conv GEMM ----------------
// KS=3: 4-buffer pipeline (prefetch distance 3, wait_group 2), stage = 16 ci,
//       X un-replicated 130 rows x 16ci (48B rows); taps = ldmatrix row shifts.
// KS=1: 3-buffer pipeline (distance 2, wait_group 1), stage = 32 ci, 80B rows.
// Stage-internal interleave: compute kstep0 FIRST, then issue next-stage loads,
// then the remaining ksteps (loads overlap kstep0's LDSM shadow).
template<int KS>
__global__ void __launch_bounds__(256, 2)
mma_conv(const __half* __restrict__ inh, const __half* __restrict__ inl,
         const __half* __restrict__ wh, const __half* __restrict__ wl,
         const float* __restrict__ bias,
         float* outF, int tmaj, __half* outH, __half* outL,
         const float* __restrict__ residual, const float* __restrict__ mask,
         int Cin, int Cout, int Tdim, float scale, int dogelu)
{
    extern __shared__ char smc[];
    constexpr int SXX = (KS == 3) ? 24 : 40;       // X row stride (halves); bytes mult of 16
    constexpr int SXW = (KS == 3) ? 56 : 40;       // W row stride (halves)
    constexpr int XPL = (KS == 3) ? 132 * 24 : 128 * 40;
    constexpr int WPL = 64 * SXW;
    constexpr int BUF = 2 * (XPL + WPL);
    constexpr int NBUF = (KS == 3) ? 4 : 3;

    const int b   = blockIdx.z;
    const int cog = blockIdx.y * 64;
    const int tg  = blockIdx.x * 128;
    const int tid = threadIdx.x;
    const int lane = tid & 31, wid = tid >> 5;
    const int wm = wid >> 2, wn = wid & 3;
    const int g = lane >> 2, th = lane & 3;

    const uint32_t smb = smem_to_u32(smc);
    const int Ktot = Cin * KS;
    const size_t xb = (size_t)b * Tdim * Cin;   // half units

    const int laneA = ((lane & 7) + ((lane >> 3) & 1) * 8) * SXW + (lane >> 4) * 8;
    const int laneB = ((lane & 7) + (lane >> 4) * 8) * SXX + ((lane >> 3) & 1) * 8;

    float c[2][4][4];
    #pragma unroll
    for (int i = 0; i < 2; i++)
        #pragma unroll
        for (int j = 0; j < 4; j++)
            #pragma unroll
            for (int k = 0; k < 4; k++) c[i][j][k] = 0.f;

    const int nst = (KS == 3) ? (Cin >> 4) : (Cin >> 5);

    auto load_stage = [&](int s, int buf) {
        const uint32_t bb = smb + 2u * (uint32_t)(buf * BUF);
        if (KS == 3) {
            const int ci0 = s * 16;
            // W: 2 planes x 64 rows x 6 chunks = 768 (L1-cached: shared across CTAs)
            #pragma unroll
            for (int it = 0; it < 3; it++) {
                int ic = it * 256 + tid;
                int plane = (ic >= 384) ? 1 : 0;
                int r = ic - plane * 384;
                int row = r / 6, ch = r - row * 6;
                const __half* src = (plane ? wl : wh) + (size_t)(cog + row) * Ktot + s * 48 + ch * 8;
                CP16A(bb + 2u * (uint32_t)(2 * XPL + plane * WPL + row * SXW + ch * 8), src);
            }
            // X: 2 planes x 130 rows x 2 chunks = 520
            #pragma unroll
            for (int it = 0; it < 3; it++) {
                int ic = it * 256 + tid;
                if (ic < 520) {
                    int plane = (ic >= 260) ? 1 : 0;
                    int r = ic - plane * 260;
                    int u = r >> 1, ch = r & 1;
                    int gt = tg - 2 + u;
                    const __half* src = (plane ? inl : inh) + xb + (size_t)gt * Cin + ci0 + ch * 8;
                    int ssz = (gt >= 0) ? 16 : 0;
                    CP16Z(bb + 2u * (uint32_t)(plane * XPL + u * SXX + ch * 8), src, ssz);
                }
            }
        } else {
            const int ci0 = s * 32;
            // W: 2 planes x 64 rows x 4 chunks = 512 (L1-cached)
            #pragma unroll
            for (int it = 0; it < 2; it++) {
                int ic = it * 256 + tid;
                int plane = ic >> 8, r = ic & 255;
                int row = r >> 2, ch = r & 3;
                const __half* src = (plane ? wl : wh) + (size_t)(cog + row) * Ktot + ci0 + ch * 8;
                CP16A(bb + 2u * (uint32_t)(2 * XPL + plane * WPL + row * SXW + ch * 8), src);
            }
            // X: 2 planes x 128 rows x 4 chunks = 1024
            #pragma unroll
            for (int it = 0; it < 4; it++) {
                int ic = it * 256 + tid;
                int plane = ic >> 9, r = ic & 511;
                int t = r >> 2, ch = r & 3;
                const __half* src = (plane ? inl : inh) + xb + (size_t)(tg + t) * Cin + ci0 + ch * 8;
                CP16(bb + 2u * (uint32_t)(plane * XPL + t * SXX + ch * 8), src);
            }
        }
    };

    auto compute_ks = [&](int buf, int ks) {
        const uint32_t bb = smb + 2u * (uint32_t)(buf * BUF);
        uint32_t ah[2][4], al[2][4], bh[4][2], bl[4][2];
        #pragma unroll
        for (int mf = 0; mf < 2; mf++) {
            uint32_t base = bb + 2u * (uint32_t)(2 * XPL + (wm * 32 + mf * 16) * SXW + ks * 16 + laneA);
            LDSM4(ah[mf][0], ah[mf][1], ah[mf][2], ah[mf][3], base);
            LDSM4(al[mf][0], al[mf][1], al[mf][2], al[mf][3], base + 2u * (uint32_t)WPL);
        }
        #pragma unroll
        for (int p = 0; p < 2; p++) {
            int rowb = wn * 32 + p * 16 + ((KS == 3) ? ks : 0);
            int colb = (KS == 3) ? 0 : ks * 16;
            uint32_t base = bb + 2u * (uint32_t)(rowb * SXX + colb + laneB);
            LDSM4(bh[2*p][0], bh[2*p][1], bh[2*p+1][0], bh[2*p+1][1], base);
            LDSM4(bl[2*p][0], bl[2*p][1], bl[2*p+1][0], bl[2*p+1][1], base + 2u * (uint32_t)XPL);
        }
        #pragma unroll
        for (int mf = 0; mf < 2; mf++)
            #pragma unroll
            for (int nf = 0; nf < 4; nf++) {
                MMA_F16(c[mf][nf], ah[mf], bh[nf]);
                MMA_F16(c[mf][nf], ah[mf], bl[nf]);
                MMA_F16(c[mf][nf], al[mf], bh[nf]);
            }
    };

    // ---- pipelined mainloop (prefetch distance NBUF-1, loads after kstep0) ----
    {
        int pre = (nst < NBUF - 1) ? nst : (NBUF - 1);
        for (int p = 0; p < pre; p++) {
            load_stage(p, p);
            asm volatile("cp.async.commit_group;");
        }
    }
    for (int s = 0; s < nst; s++) {
        if (KS == 3) {
            if (s + 2 < nst)      asm volatile("cp.async.wait_group 2;");
            else if (s + 1 < nst) asm volatile("cp.async.wait_group 1;");
            else                  asm volatile("cp.async.wait_group 0;");
        } else {
            if (s + 1 < nst)      asm volatile("cp.async.wait_group 1;");
            else                  asm volatile("cp.async.wait_group 0;");
        }
        __syncthreads();
        int buf = s % NBUF;
        compute_ks(buf, 0);                         // tensor pipe starts immediately
        if (s + NBUF - 1 < nst) {
            load_stage(s + NBUF - 1, (s + NBUF - 1) % NBUF);
            asm volatile("cp.async.commit_group;");
        }
        if (KS == 3) { compute_ks(buf, 1); compute_ks(buf, 2); }
        else         { compute_ks(buf, 1); }
    }

    // ---- epilogue ----
    #pragma unroll
    for (int mf = 0; mf < 2; mf++) {
        #pragma unroll
        for (int nf = 0; nf < 4; nf++) {
            int co0 = cog + wm * 32 + mf * 16 + g;
            int t0 = tg + wn * 32 + nf * 8 + 2 * th;
            float mk0 = mask ? mask[b * Tdim + t0] : 1.f;
            float mk1 = mask ? mask[b * Tdim + t0 + 1] : 1.f;
            #pragma unroll
            for (int half = 0; half < 2; half++) {
                int co = co0 + half * 8;
                float bi = bias[co];
                float v0 = (c[mf][nf][half * 2 + 0] + bi) * scale;
                float v1 = (c[mf][nf][half * 2 + 1] + bi) * scale;
                if (dogelu) {
                    v0 = 0.5f * v0 * (1.f + erff(v0 * 0.70710678118654752f));
                    v1 = 0.5f * v1 * (1.f + erff(v1 * 0.70710678118654752f));
                }
                size_t r0 = ((size_t)b * Tdim + t0) * Cout + co;
                size_t r1 = r0 + Cout;
                if (residual) { v0 += residual[r0]; v1 += residual[r1]; }
                if (mask) { v0 *= mk0; v1 *= mk1; }
                if (outF) {
                    if (tmaj) { outF[r0] = v0; outF[r1] = v1; }
                    else {
                        size_t o = ((size_t)b * Cout + co) * Tdim + t0;
                        outF[o] = v0; outF[o + 1] = v1;
                    }
                }
                if (outH) {
                    __half h0, l0, h1, l1;
                    split_f16(v0, h0, l0);
                    split_f16(v1, h1, l1);
                    outH[r0] = h0; outH[r1] = h1;
                    outL[r0] = l0; outL[r1] = l1;
                }
            }
        }
    }
}

// ---------------- group_by_segs (t-major) ----------------
__global__ void seg_zero(float* seg, float* cnt)
{
    int i = blockIdx.x * blockDim.x + threadIdx.x;
    if (i < (int)SZ_SEG) seg[i] = 0.f;
    if (i < (int)SZ_CNT) cnt[i] = 0.f;
}
__global__ void seg_scatter(const float* __restrict__ in, const int* __restrict__ mel2ph,
                            float* seg, float* cnt)
{
    int t = blockIdx.x, b = blockIdx.y, c = threadIdx.x;
    int ph = mel2ph[b * TT + t];
    if (ph < 1 || ph > LL) return;
    float v = in[((size_t)b * TT + t) * HH + c];
    atomicAdd(&seg[((size_t)b * (LL + 1) + ph) * HH + c], v);
    if (c == 0) atomicAdd(&cnt[b * (LL + 1) + ph], 1.f);
}
__global__ void seg_div(const float* __restrict__ seg, const float* __restrict__ cnt,
                        float* __restrict__ outg)
{
    int i = blockIdx.x * blockDim.x + threadIdx.x;   // over [b][l][c]
    if (i >= BB * LL * HH) return;
    int c = i % HH; int bl = i / HH; int l = bl % LL; int b = bl / LL;
    float s = seg[((size_t)b * (LL + 1) + l + 1) * HH + c];
    float n = fmaxf(cnt[b * (LL + 1) + l + 1], 1.f);
    outg[i] = s / n;
}

// ---------------- VQ (t-major) ----------------
__global__ void loss_init(float* loss) { if (threadIdx.x == 0) *loss = 0.f; }

__global__ void vq_kernel(const float* __restrict__ z, const float* __restrict__ cb,
                          __half* __restrict__ qh, __half* __restrict__ ql,
                          float* __restrict__ outIdx, float* loss)
{
    __shared__ float zsh[64];
    __shared__ float dsh[128];
    __shared__ int   ish[128];
    int l = blockIdx.x, b = blockIdx.y, tid = threadIdx.x;
    if (tid < 64) zsh[tid] = z[((size_t)b * LL + l) * CVQd + tid];
    __syncthreads();
    float x2 = 0.f, dot = 0.f, c2 = 0.f;
    #pragma unroll 8
    for (int c = 0; c < 64; c++) {
        float zv = zsh[c]; float cv = cb[tid * 64 + c];
        x2 += zv * zv; dot += zv * cv; c2 += cv * cv;
    }
    dsh[tid] = x2 - 2.f * dot + c2;
    ish[tid] = tid;
    __syncthreads();
    for (int s = 64; s > 0; s >>= 1) {
        if (tid < s) {
            float d2 = dsh[tid + s]; int i2 = ish[tid + s];
            if (d2 < dsh[tid] || (d2 == dsh[tid] && i2 < ish[tid])) { dsh[tid] = d2; ish[tid] = i2; }
        }
        __syncthreads();
    }
    int best = ish[0];
    __syncthreads();
    float part = 0.f;
    if (tid < 64) {
        float qv = cb[best * 64 + tid];
        size_t oi = ((size_t)b * LL + l) * CVQd + tid;
        __half h, lo;
        split_f16(qv, h, lo);
        qh[oi] = h; ql[oi] = lo;
        float dd = zsh[tid] - qv;
        part = dd * dd;
    }
    dsh[tid] = part;
    __syncthreads();
    for (int s = 64; s > 0; s >>= 1) { if (tid < s) dsh[tid] += dsh[tid + s]; __syncthreads(); }
    if (tid == 0) {
        atomicAdd(loss, dsh[0]);
        outIdx[b * LL + l] = (float)best;
    }
}

__global__ void loss_fin(const float* loss, float* out)
{
    out[0] = loss[0] * 0.25f / (float)(BB * LL * CVQd);
}

// ---------------- launch ----------------
extern "C" void kernel_launch(void* const* d_in, const int* in_sizes, int n_in,
                              void* d_out, int out_size)
{
    float* scratch = nullptr;
    cudaGetSymbolAddress((void**)&scratch, g_scratch);
    float*  bx  = scratch + O_BX;
    float*  by  = scratch + O_BY;
    __half* bnh = (__half*)(scratch + O_BNH);
    __half* bnl = (__half*)(scratch + O_BNL);
    __half* bmh = (__half*)(scratch + O_BMH);
    __half* bml = (__half*)(scratch + O_BML);
    __half* xh  = (__half*)(scratch + O_XH);
    __half* xl  = (__half*)(scratch + O_XL);
    __half* byh = (__half*)(scratch + O_BYH);
    __half* byl = (__half*)(scratch + O_BYL);
    float*  seg = scratch + O_SEG;
    float*  cnt = scratch + O_CNT;
    float*  bz  = scratch + O_BZ;
    __half* qh  = (__half*)(scratch + O_QH);
    __half* ql  = (__half*)(scratch + O_QL);
    float*  loss = scratch + O_LOSS;
    __half* wh  = (__half*)(scratch + O_WH);
    __half* wl  = (__half*)(scratch + O_WL);

    const float* x        = (const float*)d_in[0];
    const float* in_mask  = (const float*)d_in[1];
    const int*   mel2ph   = (const int*)  d_in[2];
    const float* ph_mask  = (const float*)d_in[3];
    const float* conv_in_w = (const float*)d_in[4];
    const float* conv_in_b = (const float*)d_in[5];
    const float* enc_ln_g = (const float*)d_in[6];
    const float* enc_ln_b = (const float*)d_in[7];
    const float* enc_w1   = (const float*)d_in[8];
    const float* enc_b1   = (const float*)d_in[9];
    const float* enc_w2   = (const float*)d_in[10];
    const float* enc_b2   = (const float*)d_in[11];
    const float* enc_last_g = (const float*)d_in[12];
    const float* enc_last_b = (const float*)d_in[13];
    const float* enc_post_w = (const float*)d_in[14];
    const float* enc_post_b = (const float*)d_in[15];
    const float* pn_ln_g = (const float*)d_in[16];
    const float* pn_ln_b = (const float*)d_in[17];
    const float* pn_w1   = (const float*)d_in[18];
    const float* pn_b1   = (const float*)d_in[19];
    const float* pn_w2   = (const float*)d_in[20];
    const float* pn_b2   = (const float*)d_in[21];
    const float* pn_last_g = (const float*)d_in[22];
    const float* pn_last_b = (const float*)d_in[23];
    const float* pn_post_w = (const float*)d_in[24];
    const float* pn_post_b = (const float*)d_in[25];
    const float* proj_in_w  = (const float*)d_in[26];
    const float* proj_in_b  = (const float*)d_in[27];
    const float* proj_out_w = (const float*)d_in[28];
    const float* proj_out_b = (const float*)d_in[29];
    const float* codebook   = (const float*)d_in[30];

    float* out = (float*)d_out;
    const float scale = 0.57735026918962576f;   // 3^-0.5

    // smem: KS=3: 4 buf * 2*(132*24 + 64*56) halves * 2B = 108032 B (2 CTAs/SM)
    //       KS=1: 3 buf * 2*(128*40 + 64*40) halves * 2B =  92160 B (2 CTAs/SM)
    const int SM3 = 4 * 2 * (132 * 24 + 64 * 56) * 2;
    const int SM1 = 3 * 2 * (128 * 40 + 64 * 40) * 2;
    cudaFuncSetAttribute(mma_conv<3>, cudaFuncAttributeMaxDynamicSharedMemorySize, SM3);
    cudaFuncSetAttribute(mma_conv<1>, cudaFuncAttributeMaxDynamicSharedMemorySize, SM1);

    dim3 blk(256);

    // ---- prepass (single launch) + early independent zero/init ----
    prep_all<<<dim3(15360, 10), 256>>>(x, conv_in_w, enc_w1, enc_w2, enc_post_w,
                                       pn_w1, pn_w2, pn_post_w, proj_in_w, proj_out_w,
                                       wh, wl, xh, xl);
    seg_zero<<<((int)SZ_SEG + 255)/256, 256>>>(seg, cnt);
    loss_init<<<1, 32>>>(loss);

    // ---- encoder (T = TT) ----
    mma_conv<1><<<dim3(TT/128, HH/64, BB), blk, SM1>>>(xh, xl, wh + OW_CIN, wl + OW_CIN,
        conv_in_b, bx, 1, nullptr, nullptr, nullptr, in_mask, CINP, HH, TT, 1.f, 0);
    for (int i = 0; i < NLB; i++) {
        ln_kernel<<<(BB*TT)/8, 256>>>(bx, bnh, bnl,
            enc_ln_g + i*HH, enc_ln_b + i*HH, nullptr, TT);
        mma_conv<3><<<dim3(TT/128, HH2/64, BB), blk, SM3>>>(bnh, bnl,
            wh + OW_E1 + (size_t)i*HH2*HH*3, wl + OW_E1 + (size_t)i*HH2*HH*3,
            enc_b1 + i*HH2, nullptr, 0, bmh, bml, nullptr, nullptr, HH, HH2, TT, scale, 1);
        mma_conv<1><<<dim3(TT/128, HH/64, BB), blk, SM1>>>(bmh, bml,
            wh + OW_E2 + (size_t)i*HH*HH2, wl + OW_E2 + (size_t)i*HH*HH2,
            enc_b2 + i*HH, bx, 1, nullptr, nullptr, bx, in_mask, HH2, HH, TT, 1.f, 0);
    }
    ln_kernel<<<(BB*TT)/8, 256>>>(bx, bnh, bnl, enc_last_g, enc_last_b, in_mask, TT);
    mma_conv<3><<<dim3(TT/128, HH/64, BB), blk, SM3>>>(bnh, bnl, wh + OW_EP, wl + OW_EP,
        enc_post_b, by, 1, nullptr, nullptr, nullptr, in_mask, HH, HH, TT, 1.f, 0);

    // ---- group by segments -> [b][l][c] into bx ----
    seg_scatter<<<dim3(TT, BB), HH>>>(by, mel2ph, seg, cnt);
    seg_div<<<(BB*LL*HH + 255)/256, 256>>>(seg, cnt, bx);

    // ---- postnet (T = LL) ----
    for (int i = 0; i < NLB; i++) {
        ln_kernel<<<(BB*LL)/8, 256>>>(bx, bnh, bnl,
            pn_ln_g + i*HH, pn_ln_b + i*HH, nullptr, LL);
        mma_conv<3><<<dim3(LL/128, HH2/64, BB), blk, SM3>>>(bnh, bnl,
            wh + OW_P1 + (size_t)i*HH2*HH*3, wl + OW_P1 + (size_t)i*HH2*HH*3,
            pn_b1 + i*HH2, nullptr, 0, bmh, bml, nullptr, nullptr, HH, HH2, LL, scale, 1);
        mma_conv<1><<<dim3(LL/128, HH/64, BB), blk, SM1>>>(bmh, bml,
            wh + OW_P2 + (size_t)i*HH*HH2, wl + OW_P2 + (size_t)i*HH*HH2,
            pn_b2 + i*HH, bx, 1, nullptr, nullptr, bx, ph_mask, HH2, HH, LL, 1.f, 0);
    }
    ln_kernel<<<(BB*LL)/8, 256>>>(bx, bnh, bnl, pn_last_g, pn_last_b, ph_mask, LL);
    mma_conv<3><<<dim3(LL/128, HH/64, BB), blk, SM3>>>(bnh, bnl, wh + OW_PP, wl + OW_PP,
        pn_post_b, nullptr, 0, byh, byl, nullptr, ph_mask, HH, HH, LL, 1.f, 0);

    // ---- proj_in -> VQ -> proj_out ----
    mma_conv<1><<<dim3(LL/128, 1, BB), blk, SM1>>>(byh, byl, wh + OW_PI, wl + OW_PI,
        proj_in_b, bz, 1, nullptr, nullptr, nullptr, nullptr, HH, CVQd, LL, 1.f, 0);
    vq_kernel<<<dim3(LL, BB), 128>>>(bz, codebook, qh, ql, out + (size_t)BB*HH*LL + 1, loss);
    mma_conv<1><<<dim3(LL/128, HH/64, BB), blk, SM1>>>(qh, ql, wh + OW_PO, wl + OW_PO,
        proj_out_b, out, 0, nullptr, nullptr, nullptr, nullptr, CVQd, HH, LL, 1.f, 0);
    loss_fin<<<1, 1>>>(loss, out + (size_t)BB*HH*LL);
}

// round 15
// speedup vs baseline: 1.1438x; 1.0013x over previous
#include <cuda_runtime.h>
#include <cuda_fp16.h>
#include <math.h>
#include <stdint.h>

// ---------------- problem constants ----------------
#define BB   16
#define TT   2048
#define LL   512
#define HH   256
#define HH2  512
#define CVQd 64
#define NLB  10   // NL * NB
#define CINP 96   // conv_in padded channels (80 -> 96)

// ---------------- sizes (floats) ----------------
#define SZ_BHT  ((size_t)BB*HH*TT)
#define SZ_BMT  ((size_t)BB*HH2*TT)
#define SZ_XP   ((size_t)BB*CINP*TT)
#define SZ_BHL  ((size_t)BB*HH*LL)
#define SZ_SEG  ((size_t)BB*HH*(LL+1))
#define SZ_CNT  ((size_t)BB*(LL+1))
#define SZ_BZL  ((size_t)BB*CVQd*LL)

// weight plane sizes (elements)
#define WSZ_CIN ((size_t)HH*CINP)
#define WSZ_E1  ((size_t)NLB*HH2*HH*3)
#define WSZ_E2  ((size_t)NLB*HH*HH2)
#define WSZ_EP  ((size_t)HH*HH*3)
#define WSZ_PI  ((size_t)CVQd*HH)
#define WSZ_PO  ((size_t)HH*CVQd)
#define WTOT    (WSZ_CIN + 2*(WSZ_E1 + WSZ_E2 + WSZ_EP) + WSZ_PI + WSZ_PO)

// scratch offsets (float units). half planes take size/2 floats.
// ALL activation tensors are t-major: [b][t][c].
#define O_BX   ((size_t)0)
#define O_BY   (O_BX  + SZ_BHT)
#define O_BNH  (O_BY  + SZ_BHT)
#define O_BNL  (O_BNH + SZ_BHT/2)
#define O_BMH  (O_BNL + SZ_BHT/2)
#define O_BML  (O_BMH + SZ_BMT/2)
#define O_XH   (O_BML + SZ_BMT/2)
#define O_XL   (O_XH  + SZ_XP/2)
#define O_BYH  (O_XL  + SZ_XP/2)
#define O_BYL  (O_BYH + SZ_BHL/2)
#define O_SEG  (O_BYL + SZ_BHL/2)
#define O_CNT  (O_SEG + SZ_SEG)
#define O_BZ   (O_CNT + SZ_CNT)
#define O_QH   (O_BZ  + SZ_BZL)
#define O_QL   (O_QH  + SZ_BZL/2)
#define O_LOSS (O_QL  + SZ_BZL/2)
#define O_WH   (O_LOSS + 16)
#define O_WL   (O_WH  + WTOT/2)
#define SCRATCH_TOT (O_WL + WTOT/2)

__device__ __align__(16) float g_scratch[SCRATCH_TOT];

// weight offsets inside wh/wl planes (element units)
#define OW_CIN ((size_t)0)
#define OW_E1  (OW_CIN + WSZ_CIN)
#define OW_E2  (OW_E1 + WSZ_E1)
#define OW_EP  (OW_E2 + WSZ_E2)
#define OW_P1  (OW_EP + WSZ_EP)
#define OW_P2  (OW_P1 + WSZ_E1)
#define OW_PP  (OW_P2 + WSZ_E2)
#define OW_PI  (OW_PP + WSZ_EP)
#define OW_PO  (OW_PI + WSZ_PI)

// ---------------- helpers ----------------
__device__ __forceinline__ uint32_t smem_to_u32(const void* p) {
    uint32_t a;
    asm("{ .reg .u64 t; cvta.to.shared.u64 t, %1; cvt.u32.u64 %0, t; }" : "=r"(a) : "l"(p));
    return a;
}
#define CP16(dst, src) \
    asm volatile("cp.async.cg.shared.global [%0], [%1], 16;" :: "r"(dst), "l"(src))
#define CP16A(dst, src) \
    asm volatile("cp.async.ca.shared.global [%0], [%1], 16;" :: "r"(dst), "l"(src))
#define CP16Z(dst, src, ssz) \
    asm volatile("cp.async.cg.shared.global [%0], [%1], 16, %2;" :: "r"(dst), "l"(src), "r"(ssz))

#define LDSM4(r0, r1, r2, r3, addr)                                              \
    asm volatile("ldmatrix.sync.aligned.m8n8.x4.shared.b16 {%0,%1,%2,%3}, [%4];" \
        : "=r"(r0), "=r"(r1), "=r"(r2), "=r"(r3) : "r"(addr))

#define MMA_F16(C, A, B)                                                         \
    asm volatile("mma.sync.aligned.m16n8k16.row.col.f32.f16.f16.f32 "            \
        "{%0,%1,%2,%3}, {%4,%5,%6,%7}, {%8,%9}, {%0,%1,%2,%3};"                  \
        : "+f"((C)[0]), "+f"((C)[1]), "+f"((C)[2]), "+f"((C)[3])                  \
        : "r"((A)[0]), "r"((A)[1]), "r"((A)[2]), "r"((A)[3]),                     \
          "r"((B)[0]), "r"((B)[1]))

__device__ __forceinline__ void split_f16(float v, __half& h, __half& l)
{
    h = __float2half_rn(v);
    l = __float2half_rn(v - __half2float(h));
}

// ---------------- merged prepass ----------------
__device__ __forceinline__ void prep_one(const float* __restrict__ w,
                                         __half* __restrict__ oh, __half* __restrict__ ol,
                                         int total, int Cout, int Cin, int KS, int idx)
{
    if (idx >= total) return;
    int per_layer = Cout * Cin * KS;
    int layer = idx / per_layer;
    int r = idx - layer * per_layer;
    int co = r / (Cin * KS);
    int r2 = r - co * (Cin * KS);
    int ci = r2 / KS;
    int tap = r2 - ci * KS;
    __half h, l;
    split_f16(w[idx], h, l);
    int kidx = (ci >> 4) * (16 * KS) + tap * 16 + (ci & 15);
    size_t o = ((size_t)layer * Cout + co) * (size_t)(Cin * KS) + kidx;
    oh[o] = h; ol[o] = l;
}

__global__ void prep_all(
    const float* __restrict__ x,
    const float* __restrict__ cinw, const float* __restrict__ e1,
    const float* __restrict__ e2,  const float* __restrict__ ep,
    const float* __restrict__ p1,  const float* __restrict__ p2,
    const float* __restrict__ pp,  const float* __restrict__ pi,
    const float* __restrict__ po,
    __half* __restrict__ wh, __half* __restrict__ wl,
    __half* __restrict__ xh, __half* __restrict__ xl)
{
    int idx = blockIdx.x * 256 + threadIdx.x;
    switch (blockIdx.y) {
    case 0:  // conv_in weights padded 80 -> 96 ci (KS=1, kidx = ci)
        if (idx < (int)WSZ_CIN) {
            int co = idx / CINP, ci = idx - co * CINP;
            float v = (ci < 80) ? cinw[co * 80 + ci] : 0.f;
            __half h, l;
            split_f16(v, h, l);
            wh[OW_CIN + idx] = h; wl[OW_CIN + idx] = l;
        }
        break;
    case 1: prep_one(e1, wh + OW_E1, wl + OW_E1, (int)WSZ_E1, HH2, HH, 3, idx); break;
    case 2: prep_one(e2, wh + OW_E2, wl + OW_E2, (int)WSZ_E2, HH, HH2, 1, idx); break;
    case 3: prep_one(ep, wh + OW_EP, wl + OW_EP, (int)WSZ_EP, HH, HH, 3, idx); break;
    case 4: prep_one(p1, wh + OW_P1, wl + OW_P1, (int)WSZ_E1, HH2, HH, 3, idx); break;
    case 5: prep_one(p2, wh + OW_P2, wl + OW_P2, (int)WSZ_E2, HH, HH2, 1, idx); break;
    case 6: prep_one(pp, wh + OW_PP, wl + OW_PP, (int)WSZ_EP, HH, HH, 3, idx); break;
    case 7: prep_one(pi, wh + OW_PI, wl + OW_PI, (int)WSZ_PI, CVQd, HH, 1, idx); break;
    case 8: prep_one(po, wh + OW_PO, wl + OW_PO, (int)WSZ_PO, HH, CVQd, 1, idx); break;
    default:  // x -> 96-channel t-major planes (zero-padded)
        if (idx < (int)SZ_XP) {
            int b = idx / (CINP * TT);
            int r = idx - b * CINP * TT;
            int t = r / CINP, c = r - t * CINP;
            float v = (c < 80) ? x[((size_t)b * 80 + c) * TT + t] : 0.f;
            __half h, l;
            split_f16(v, h, l);
            size_t o = ((size_t)b * TT + t) * CINP + c;
            xh[o] = h; xl[o] = l;
        }
        break;
    }
}

// ---------------- LayerNorm (t-major): warp per row ----------------
__global__ void ln_kernel(const float* __restrict__ in, __half* __restrict__ outh,
                          __half* __restrict__ outl,
                          const float* __restrict__ gma, const float* __restrict__ bta,
                          const float* __restrict__ mask, int Tdim)
{
    int row = blockIdx.x * 8 + (threadIdx.x >> 5);
    if (row >= BB * Tdim) return;
    int lane = threadIdx.x & 31;
    const float4* p = (const float4*)(in + (size_t)row * HH) + lane * 2;
    float4 a = p[0], q = p[1];
    float v[8] = {a.x, a.y, a.z, a.w, q.x, q.y, q.z, q.w};
    float s = 0.f, s2 = 0.f;
    #pragma unroll
    for (int i = 0; i < 8; i++) { s += v[i]; s2 += v[i] * v[i]; }
    #pragma unroll
    for (int o = 16; o; o >>= 1) {
        s  += __shfl_xor_sync(0xffffffffu, s, o);
        s2 += __shfl_xor_sync(0xffffffffu, s2, o);
    }
    float mean = s * (1.f / HH);
    float var  = s2 * (1.f / HH) - mean * mean;
    float r = rsqrtf(var + 1e-5f);
    float mk = mask ? mask[row] : 1.f;
    __half2 hv[4], lv[4];
    #pragma unroll
    for (int i = 0; i < 4; i++) {
        int c = lane * 8 + 2 * i;
        float n0 = ((v[2*i]   - mean) * r * gma[c]     + bta[c])     * mk;
        float n1 = ((v[2*i+1] - mean) * r * gma[c + 1] + bta[c + 1]) * mk;
        __half h0, l0, h1, l1;
        split_f16(n0, h0, l0);
        split_f16(n1, h1, l1);
        hv[i] = __halves2half2(h0, h1);
        lv[i] = __halves2half2(l0, l1);
    }
    *(uint4*)(outh + (size_t)row * HH + lane * 8) = *(uint4*)hv;
    *(uint4*)(outl + (size_t)row * HH + lane * 8) = *(uint4*)lv;
}

// ---------------- fp16-split mma.sync conv GEMM ----------------
// KS=3: 4-buffer pipeline (prefetch distance 3, wait_group 2), stage = 16 ci,
//       X un-replicated 130 rows x 16ci (48B rows); taps = ldmatrix row shifts.
// KS=1: 3-buffer pipeline (distance 2, wait_group 1), stage = 32 ci, 80B rows.
// Intra-stage: compute kstep0 first, then next-stage loads, then remaining ksteps.
// Split-term loop is OUTERMOST in the MMA block: accumulator RAW distance = 8 MMAs.
template<int KS>
__global__ void __launch_bounds__(256, 2)
mma_conv(const __half* __restrict__ inh, const __half* __restrict__ inl,
         const __half* __restrict__ wh, const __half* __restrict__ wl,
         const float* __restrict__ bias,
         float* outF, int tmaj, __half* outH, __half* outL,
         const float* __restrict__ residual, const float* __restrict__ mask,
         int Cin, int Cout, int Tdim, float scale, int dogelu)
{
    extern __shared__ char smc[];
    constexpr int SXX = (KS == 3) ? 24 : 40;       // X row stride (halves); bytes mult of 16
    constexpr int SXW = (KS == 3) ? 56 : 40;       // W row stride (halves)
    constexpr int XPL = (KS == 3) ? 132 * 24 : 128 * 40;
    constexpr int WPL = 64 * SXW;
    constexpr int BUF = 2 * (XPL + WPL);
    constexpr int NBUF = (KS == 3) ? 4 : 3;

    const int b   = blockIdx.z;
    const int cog = blockIdx.y * 64;
    const int tg  = blockIdx.x * 128;
    const int tid = threadIdx.x;
    const int lane = tid & 31, wid = tid >> 5;
    const int wm = wid >> 2, wn = wid & 3;
    const int g = lane >> 2, th = lane & 3;

    const uint32_t smb = smem_to_u32(smc);
    const int Ktot = Cin * KS;
    const size_t xb = (size_t)b * Tdim * Cin;   // half units

    const int laneA = ((lane & 7) + ((lane >> 3) & 1) * 8) * SXW + (lane >> 4) * 8;
    const int laneB = ((lane & 7) + (lane >> 4) * 8) * SXX + ((lane >> 3) & 1) * 8;

    float c[2][4][4];
    #pragma unroll
    for (int i = 0; i < 2; i++)
        #pragma unroll
        for (int j = 0; j < 4; j++)
            #pragma unroll
            for (int k = 0; k < 4; k++) c[i][j][k] = 0.f;

    const int nst = (KS == 3) ? (Cin >> 4) : (Cin >> 5);

    auto load_stage = [&](int s, int buf) {
        const uint32_t bb = smb + 2u * (uint32_t)(buf * BUF);
        if (KS == 3) {
            const int ci0 = s * 16;
            // W: 2 planes x 64 rows x 6 chunks = 768 (L1-cached: shared across CTAs)
            #pragma unroll
            for (int it = 0; it < 3; it++) {
                int ic = it * 256 + tid;
                int plane = (ic >= 384) ? 1 : 0;
                int r = ic - plane * 384;
                int row = r / 6, ch = r - row * 6;
                const __half* src = (plane ? wl : wh) + (size_t)(cog + row) * Ktot + s * 48 + ch * 8;
                CP16A(bb + 2u * (uint32_t)(2 * XPL + plane * WPL + row * SXW + ch * 8), src);
            }
            // X: 2 planes x 130 rows x 2 chunks = 520
            #pragma unroll
            for (int it = 0; it < 3; it++) {
                int ic = it * 256 + tid;
                if (ic < 520) {
                    int plane = (ic >= 260) ? 1 : 0;
                    int r = ic - plane * 260;
                    int u = r >> 1, ch = r & 1;
                    int gt = tg - 2 + u;
                    const __half* src = (plane ? inl : inh) + xb + (size_t)gt * Cin + ci0 + ch * 8;
                    int ssz = (gt >= 0) ? 16 : 0;
                    CP16Z(bb + 2u * (uint32_t)(plane * XPL + u * SXX + ch * 8), src, ssz);
                }
            }
        } else {
            const int ci0 = s * 32;
            // W: 2 planes x 64 rows x 4 chunks = 512 (L1-cached)
            #pragma unroll
            for (int it = 0; it < 2; it++) {
                int ic = it * 256 + tid;
                int plane = ic >> 8, r = ic & 255;
                int row = r >> 2, ch = r & 3;
                const __half* src = (plane ? wl : wh) + (size_t)(cog + row) * Ktot + ci0 + ch * 8;
                CP16A(bb + 2u * (uint32_t)(2 * XPL + plane * WPL + row * SXW + ch * 8), src);
            }
            // X: 2 planes x 128 rows x 4 chunks = 1024
            #pragma unroll
            for (int it = 0; it < 4; it++) {
                int ic = it * 256 + tid;
                int plane = ic >> 9, r = ic & 511;
                int t = r >> 2, ch = r & 3;
                const __half* src = (plane ? inl : inh) + xb + (size_t)(tg + t) * Cin + ci0 + ch * 8;
                CP16(bb + 2u * (uint32_t)(plane * XPL + t * SXX + ch * 8), src);
            }
        }
    };

    auto compute_ks = [&](int buf, int ks) {
        const uint32_t bb = smb + 2u * (uint32_t)(buf * BUF);
        uint32_t ah[2][4], al[2][4], bh[4][2], bl[4][2];
        #pragma unroll
        for (int mf = 0; mf < 2; mf++) {
            uint32_t base = bb + 2u * (uint32_t)(2 * XPL + (wm * 32 + mf * 16) * SXW + ks * 16 + laneA);
            LDSM4(ah[mf][0], ah[mf][1], ah[mf][2], ah[mf][3], base);
            LDSM4(al[mf][0], al[mf][1], al[mf][2], al[mf][3], base + 2u * (uint32_t)WPL);
        }
        #pragma unroll
        for (int p = 0; p < 2; p++) {
            int rowb = wn * 32 + p * 16 + ((KS == 3) ? ks : 0);
            int colb = (KS == 3) ? 0 : ks * 16;
            uint32_t base = bb + 2u * (uint32_t)(rowb * SXX + colb + laneB);
            LDSM4(bh[2*p][0], bh[2*p][1], bh[2*p+1][0], bh[2*p+1][1], base);
            LDSM4(bl[2*p][0], bl[2*p][1], bl[2*p+1][0], bl[2*p+1][1], base + 2u * (uint32_t)XPL);
        }
        // split-term outermost: accumulator RAW distance = 8 independent MMAs
        #pragma unroll
        for (int mf = 0; mf < 2; mf++)
            #pragma unroll
            for (int nf = 0; nf < 4; nf++)
                MMA_F16(c[mf][nf], ah[mf], bh[nf]);
        #pragma unroll
        for (int mf = 0; mf < 2; mf++)
            #pragma unroll
            for (int nf = 0; nf < 4; nf++)
                MMA_F16(c[mf][nf], ah[mf], bl[nf]);
        #pragma unroll
        for (int mf = 0; mf < 2; mf++)
            #pragma unroll
            for (int nf = 0; nf < 4; nf++)
                MMA_F16(c[mf][nf], al[mf], bh[nf]);
    };

    // ---- pipelined mainloop (prefetch distance NBUF-1, loads after kstep0) ----
    {
        int pre = (nst < NBUF - 1) ? nst : (NBUF - 1);
        for (int p = 0; p < pre; p++) {
            load_stage(p, p);
            asm volatile("cp.async.commit_group;");
        }
    }
    for (int s = 0; s < nst; s++) {
        if (KS == 3) {
            if (s + 2 < nst)      asm volatile("cp.async.wait_group 2;");
            else if (s + 1 < nst) asm volatile("cp.async.wait_group 1;");
            else                  asm volatile("cp.async.wait_group 0;");
        } else {
            if (s + 1 < nst)      asm volatile("cp.async.wait_group 1;");
            else                  asm volatile("cp.async.wait_group 0;");
        }
        __syncthreads();
        int buf = s % NBUF;
        compute_ks(buf, 0);                         // tensor pipe starts immediately
        if (s + NBUF - 1 < nst) {
            load_stage(s + NBUF - 1, (s + NBUF - 1) % NBUF);
            asm volatile("cp.async.commit_group;");
        }
        if (KS == 3) { compute_ks(buf, 1); compute_ks(buf, 2); }
        else         { compute_ks(buf, 1); }
    }

    // ---- epilogue ----
    #pragma unroll
    for (int mf = 0; mf < 2; mf++) {
        #pragma unroll
        for (int nf = 0; nf < 4; nf++) {
            int co0 = cog + wm * 32 + mf * 16 + g;
            int t0 = tg + wn * 32 + nf * 8 + 2 * th;
            float mk0 = mask ? mask[b * Tdim + t0] : 1.f;
            float mk1 = mask ? mask[b * Tdim + t0 + 1] : 1.f;
            #pragma unroll
            for (int half = 0; half < 2; half++) {
                int co = co0 + half * 8;
                float bi = bias[co];
                float v0 = (c[mf][nf][half * 2 + 0] + bi) * scale;
                float v1 = (c[mf][nf][half * 2 + 1] + bi) * scale;
                if (dogelu) {
                    v0 = 0.5f * v0 * (1.f + erff(v0 * 0.70710678118654752f));
                    v1 = 0.5f * v1 * (1.f + erff(v1 * 0.70710678118654752f));
                }
                size_t r0 = ((size_t)b * Tdim + t0) * Cout + co;
                size_t r1 = r0 + Cout;
                if (residual) { v0 += residual[r0]; v1 += residual[r1]; }
                if (mask) { v0 *= mk0; v1 *= mk1; }
                if (outF) {
                    if (tmaj) { outF[r0] = v0; outF[r1] = v1; }
                    else {
                        size_t o = ((size_t)b * Cout + co) * Tdim + t0;
                        outF[o] = v0; outF[o + 1] = v1;
                    }
                }
                if (outH) {
                    __half h0, l0, h1, l1;
                    split_f16(v0, h0, l0);
                    split_f16(v1, h1, l1);
                    outH[r0] = h0; outH[r1] = h1;
                    outL[r0] = l0; outL[r1] = l1;
                }
            }
        }
    }
}

// ---------------- group_by_segs (t-major) ----------------
__global__ void seg_zero(float* seg, float* cnt)
{
    int i = blockIdx.x * blockDim.x + threadIdx.x;
    if (i < (int)SZ_SEG) seg[i] = 0.f;
    if (i < (int)SZ_CNT) cnt[i] = 0.f;
}
__global__ void seg_scatter(const float* __restrict__ in, const int* __restrict__ mel2ph,
                            float* seg, float* cnt)
{
    int t = blockIdx.x, b = blockIdx.y, c = threadIdx.x;
    int ph = mel2ph[b * TT + t];
    if (ph < 1 || ph > LL) return;
    float v = in[((size_t)b * TT + t) * HH + c];
    atomicAdd(&seg[((size_t)b * (LL + 1) + ph) * HH + c], v);
    if (c == 0) atomicAdd(&cnt[b * (LL + 1) + ph], 1.f);
}
__global__ void seg_div(const float* __restrict__ seg, const float* __restrict__ cnt,
                        float* __restrict__ outg)
{
    int i = blockIdx.x * blockDim.x + threadIdx.x;   // over [b][l][c]
    if (i >= BB * LL * HH) return;
    int c = i % HH; int bl = i / HH; int l = bl % LL; int b = bl / LL;
    float s = seg[((size_t)b * (LL + 1) + l + 1) * HH + c];
    float n = fmaxf(cnt[b * (LL + 1) + l + 1], 1.f);
    outg[i] = s / n;
}

// ---------------- VQ (t-major) ----------------
__global__ void loss_init(float* loss) { if (threadIdx.x == 0) *loss = 0.f; }

__global__ void vq_kernel(const float* __restrict__ z, const float* __restrict__ cb,
                          __half* __restrict__ qh, __half* __restrict__ ql,
                          float* __restrict__ outIdx, float* loss)
{
    __shared__ float zsh[64];
    __shared__ float dsh[128];
    __shared__ int   ish[128];
    int l = blockIdx.x, b = blockIdx.y, tid = threadIdx.x;
    if (tid < 64) zsh[tid] = z[((size_t)b * LL + l) * CVQd + tid];
    __syncthreads();
    float x2 = 0.f, dot = 0.f, c2 = 0.f;
    #pragma unroll 8
    for (int c = 0; c < 64; c++) {
        float zv = zsh[c]; float cv = cb[tid * 64 + c];
        x2 += zv * zv; dot += zv * cv; c2 += cv * cv;
    }
    dsh[tid] = x2 - 2.f * dot + c2;
    ish[tid] = tid;
    __syncthreads();
    for (int s = 64; s > 0; s >>= 1) {
        if (tid < s) {
            float d2 = dsh[tid + s]; int i2 = ish[tid + s];
            if (d2 < dsh[tid] || (d2 == dsh[tid] && i2 < ish[tid])) { dsh[tid] = d2; ish[tid] = i2; }
        }
        __syncthreads();
    }
    int best = ish[0];
    __syncthreads();
    float part = 0.f;
    if (tid < 64) {
        float qv = cb[best * 64 + tid];
        size_t oi = ((size_t)b * LL + l) * CVQd + tid;
        __half h, lo;
        split_f16(qv, h, lo);
        qh[oi] = h; ql[oi] = lo;
        float dd = zsh[tid] - qv;
        part = dd * dd;
    }
    dsh[tid] = part;
    __syncthreads();
    for (int s = 64; s > 0; s >>= 1) { if (tid < s) dsh[tid] += dsh[tid + s]; __syncthreads(); }
    if (tid == 0) {
        atomicAdd(loss, dsh[0]);
        outIdx[b * LL + l] = (float)best;
    }
}

__global__ void loss_fin(const float* loss, float* out)
{
    out[0] = loss[0] * 0.25f / (float)(BB * LL * CVQd);
}

// ---------------- launch ----------------
extern "C" void kernel_launch(void* const* d_in, const int* in_sizes, int n_in,
                              void* d_out, int out_size)
{
    float* scratch = nullptr;
    cudaGetSymbolAddress((void**)&scratch, g_scratch);
    float*  bx  = scratch + O_BX;
    float*  by  = scratch + O_BY;
    __half* bnh = (__half*)(scratch + O_BNH);
    __half* bnl = (__half*)(scratch + O_BNL);
    __half* bmh = (__half*)(scratch + O_BMH);
    __half* bml = (__half*)(scratch + O_BML);
    __half* xh  = (__half*)(scratch + O_XH);
    __half* xl  = (__half*)(scratch + O_XL);
    __half* byh = (__half*)(scratch + O_BYH);
    __half* byl = (__half*)(scratch + O_BYL);
    float*  seg = scratch + O_SEG;
    float*  cnt = scratch + O_CNT;
    float*  bz  = scratch + O_BZ;
    __half* qh  = (__half*)(scratch + O_QH);
    __half* ql  = (__half*)(scratch + O_QL);
    float*  loss = scratch + O_LOSS;
    __half* wh  = (__half*)(scratch + O_WH);
    __half* wl  = (__half*)(scratch + O_WL);

    const float* x        = (const float*)d_in[0];
    const float* in_mask  = (const float*)d_in[1];
    const int*   mel2ph   = (const int*)  d_in[2];
    const float* ph_mask  = (const float*)d_in[3];
    const float* conv_in_w = (const float*)d_in[4];
    const float* conv_in_b = (const float*)d_in[5];
    const float* enc_ln_g = (const float*)d_in[6];
    const float* enc_ln_b = (const float*)d_in[7];
    const float* enc_w1   = (const float*)d_in[8];
    const float* enc_b1   = (const float*)d_in[9];
    const float* enc_w2   = (const float*)d_in[10];
    const float* enc_b2   = (const float*)d_in[11];
    const float* enc_last_g = (const float*)d_in[12];
    const float* enc_last_b = (const float*)d_in[13];
    const float* enc_post_w = (const float*)d_in[14];
    const float* enc_post_b = (const float*)d_in[15];
    const float* pn_ln_g = (const float*)d_in[16];
    const float* pn_ln_b = (const float*)d_in[17];
    const float* pn_w1   = (const float*)d_in[18];
    const float* pn_b1   = (const float*)d_in[19];
    const float* pn_w2   = (const float*)d_in[20];
    const float* pn_b2   = (const float*)d_in[21];
    const float* pn_last_g = (const float*)d_in[22];
    const float* pn_last_b = (const float*)d_in[23];
    const float* pn_post_w = (const float*)d_in[24];
    const float* pn_post_b = (const float*)d_in[25];
    const float* proj_in_w  = (const float*)d_in[26];
    const float* proj_in_b  = (const float*)d_in[27];
    const float* proj_out_w = (const float*)d_in[28];
    const float* proj_out_b = (const float*)d_in[29];
    const float* codebook   = (const float*)d_in[30];

    float* out = (float*)d_out;
    const float scale = 0.57735026918962576f;   // 3^-0.5

    // smem: KS=3: 4 buf * 2*(132*24 + 64*56) halves * 2B = 108032 B (2 CTAs/SM)
    //       KS=1: 3 buf * 2*(128*40 + 64*40) halves * 2B =  92160 B (2 CTAs/SM)
    const int SM3 = 4 * 2 * (132 * 24 + 64 * 56) * 2;
    const int SM1 = 3 * 2 * (128 * 40 + 64 * 40) * 2;
    cudaFuncSetAttribute(mma_conv<3>, cudaFuncAttributeMaxDynamicSharedMemorySize, SM3);
    cudaFuncSetAttribute(mma_conv<1>, cudaFuncAttributeMaxDynamicSharedMemorySize, SM1);

    dim3 blk(256);

    // ---- prepass (single launch) + early independent zero/init ----
    prep_all<<<dim3(15360, 10), 256>>>(x, conv_in_w, enc_w1, enc_w2, enc_post_w,
                                       pn_w1, pn_w2, pn_post_w, proj_in_w, proj_out_w,
                                       wh, wl, xh, xl);
    seg_zero<<<((int)SZ_SEG + 255)/256, 256>>>(seg, cnt);
    loss_init<<<1, 32>>>(loss);

    // ---- encoder (T = TT) ----
    mma_conv<1><<<dim3(TT/128, HH/64, BB), blk, SM1>>>(xh, xl, wh + OW_CIN, wl + OW_CIN,
        conv_in_b, bx, 1, nullptr, nullptr, nullptr, in_mask, CINP, HH, TT, 1.f, 0);
    for (int i = 0; i < NLB; i++) {
        ln_kernel<<<(BB*TT)/8, 256>>>(bx, bnh, bnl,
            enc_ln_g + i*HH, enc_ln_b + i*HH, nullptr, TT);
        mma_conv<3><<<dim3(TT/128, HH2/64, BB), blk, SM3>>>(bnh, bnl,
            wh + OW_E1 + (size_t)i*HH2*HH*3, wl + OW_E1 + (size_t)i*HH2*HH*3,
            enc_b1 + i*HH2, nullptr, 0, bmh, bml, nullptr, nullptr, HH, HH2, TT, scale, 1);
        mma_conv<1><<<dim3(TT/128, HH/64, BB), blk, SM1>>>(bmh, bml,
            wh + OW_E2 + (size_t)i*HH*HH2, wl + OW_E2 + (size_t)i*HH*HH2,
            enc_b2 + i*HH, bx, 1, nullptr, nullptr, bx, in_mask, HH2, HH, TT, 1.f, 0);
    }
    ln_kernel<<<(BB*TT)/8, 256>>>(bx, bnh, bnl, enc_last_g, enc_last_b, in_mask, TT);
    mma_conv<3><<<dim3(TT/128, HH/64, BB), blk, SM3>>>(bnh, bnl, wh + OW_EP, wl + OW_EP,
        enc_post_b, by, 1, nullptr, nullptr, nullptr, in_mask, HH, HH, TT, 1.f, 0);

    // ---- group by segments -> [b][l][c] into bx ----
    seg_scatter<<<dim3(TT, BB), HH>>>(by, mel2ph, seg, cnt);
    seg_div<<<(BB*LL*HH + 255)/256, 256>>>(seg, cnt, bx);

    // ---- postnet (T = LL) ----
    for (int i = 0; i < NLB; i++) {
        ln_kernel<<<(BB*LL)/8, 256>>>(bx, bnh, bnl,
            pn_ln_g + i*HH, pn_ln_b + i*HH, nullptr, LL);
        mma_conv<3><<<dim3(LL/128, HH2/64, BB), blk, SM3>>>(bnh, bnl,
            wh + OW_P1 + (size_t)i*HH2*HH*3, wl + OW_P1 + (size_t)i*HH2*HH*3,
            pn_b1 + i*HH2, nullptr, 0, bmh, bml, nullptr, nullptr, HH, HH2, LL, scale, 1);
        mma_conv<1><<<dim3(LL/128, HH/64, BB), blk, SM1>>>(bmh, bml,
            wh + OW_P2 + (size_t)i*HH*HH2, wl + OW_P2 + (size_t)i*HH*HH2,
            pn_b2 + i*HH, bx, 1, nullptr, nullptr, bx, ph_mask, HH2, HH, LL, 1.f, 0);
    }
    ln_kernel<<<(BB*LL)/8, 256>>>(bx, bnh, bnl, pn_last_g, pn_last_b, ph_mask, LL);
    mma_conv<3><<<dim3(LL/128, HH/64, BB), blk, SM3>>>(bnh, bnl, wh + OW_PP, wl + OW_PP,
        pn_post_b, nullptr, 0, byh, byl, nullptr, ph_mask, HH, HH, LL, 1.f, 0);

    // ---- proj_in -> VQ -> proj_out ----
    mma_conv<1><<<dim3(LL/128, 1, BB), blk, SM1>>>(byh, byl, wh + OW_PI, wl + OW_PI,
        proj_in_b, bz, 1, nullptr, nullptr, nullptr, nullptr, HH, CVQd, LL, 1.f, 0);
    vq_kernel<<<dim3(LL, BB), 128>>>(bz, codebook, qh, ql, out + (size_t)BB*HH*LL + 1, loss);
    mma_conv<1><<<dim3(LL/128, HH/64, BB), blk, SM1>>>(qh, ql, wh + OW_PO, wl + OW_PO,
        proj_out_b, out, 0, nullptr, nullptr, nullptr, nullptr, CVQd, HH, LL, 1.f, 0);
    loss_fin<<<1, 1>>>(loss, out + (size_t)BB*HH*LL);
}

// round 16
// speedup vs baseline: 1.1463x; 1.0023x over previous
#include <cuda_runtime.h>
#include <cuda_fp16.h>
#include <math.h>
#include <stdint.h>

// ---------------- problem constants ----------------
#define BB   16
#define TT   2048
#define LL   512
#define HH   256
#define HH2  512
#define CVQd 64
#define NLB  10   // NL * NB
#define CINP 96   // conv_in padded channels (80 -> 96)

// ---------------- sizes (floats) ----------------
#define SZ_BHT  ((size_t)BB*HH*TT)
#define SZ_BMT  ((size_t)BB*HH2*TT)
#define SZ_XP   ((size_t)BB*CINP*TT)
#define SZ_BHL  ((size_t)BB*HH*LL)
#define SZ_SEG  ((size_t)BB*HH*(LL+1))
#define SZ_CNT  ((size_t)BB*(LL+1))
#define SZ_BZL  ((size_t)BB*CVQd*LL)

// weight plane sizes (elements)
#define WSZ_CIN ((size_t)HH*CINP)
#define WSZ_E1  ((size_t)NLB*HH2*HH*3)
#define WSZ_E2  ((size_t)NLB*HH*HH2)
#define WSZ_EP  ((size_t)HH*HH*3)
#define WSZ_PI  ((size_t)CVQd*HH)
#define WSZ_PO  ((size_t)HH*CVQd)
#define WTOT    (WSZ_CIN + 2*(WSZ_E1 + WSZ_E2 + WSZ_EP) + WSZ_PI + WSZ_PO)

// scratch offsets (float units). half planes take size/2 floats.
// ALL activation tensors are t-major: [b][t][c].
#define O_BX   ((size_t)0)
#define O_BY   (O_BX  + SZ_BHT)
#define O_BNH  (O_BY  + SZ_BHT)
#define O_BNL  (O_BNH + SZ_BHT/2)
#define O_BMH  (O_BNL + SZ_BHT/2)
#define O_BML  (O_BMH + SZ_BMT/2)
#define O_XH   (O_BML + SZ_BMT/2)
#define O_XL   (O_XH  + SZ_XP/2)
#define O_BYH  (O_XL  + SZ_XP/2)
#define O_BYL  (O_BYH + SZ_BHL/2)
#define O_SEG  (O_BYL + SZ_BHL/2)
#define O_CNT  (O_SEG + SZ_SEG)
#define O_BZ   (O_CNT + SZ_CNT)
#define O_QH   (O_BZ  + SZ_BZL)
#define O_QL   (O_QH  + SZ_BZL/2)
#define O_LOSS (O_QL  + SZ_BZL/2)
#define O_WH   (O_LOSS + 16)
#define O_WL   (O_WH  + WTOT/2)
#define SCRATCH_TOT (O_WL + WTOT/2)

__device__ __align__(16) float g_scratch[SCRATCH_TOT];

// weight offsets inside wh/wl planes (element units)
#define OW_CIN ((size_t)0)
#define OW_E1  (OW_CIN + WSZ_CIN)
#define OW_E2  (OW_E1 + WSZ_E1)
#define OW_EP  (OW_E2 + WSZ_E2)
#define OW_P1  (OW_EP + WSZ_EP)
#define OW_P2  (OW_P1 + WSZ_E1)
#define OW_PP  (OW_P2 + WSZ_E2)
#define OW_PI  (OW_PP + WSZ_EP)
#define OW_PO  (OW_PI + WSZ_PI)

// ---------------- helpers ----------------
__device__ __forceinline__ uint32_t smem_to_u32(const void* p) {
    uint32_t a;
    asm("{ .reg .u64 t; cvta.to.shared.u64 t, %1; cvt.u32.u64 %0, t; }" : "=r"(a) : "l"(p));
    return a;
}
#define CP16(dst, src) \
    asm volatile("cp.async.cg.shared.global [%0], [%1], 16;" :: "r"(dst), "l"(src))
#define CP16A(dst, src) \
    asm volatile("cp.async.ca.shared.global [%0], [%1], 16;" :: "r"(dst), "l"(src))
#define CP16Z(dst, src, ssz) \
    asm volatile("cp.async.cg.shared.global [%0], [%1], 16, %2;" :: "r"(dst), "l"(src), "r"(ssz))

#define LDSM4(r0, r1, r2, r3, addr)                                              \
    asm volatile("ldmatrix.sync.aligned.m8n8.x4.shared.b16 {%0,%1,%2,%3}, [%4];" \
        : "=r"(r0), "=r"(r1), "=r"(r2), "=r"(r3) : "r"(addr))

#define MMA_F16(C, A, B)                                                         \
    asm volatile("mma.sync.aligned.m16n8k16.row.col.f32.f16.f16.f32 "            \
        "{%0,%1,%2,%3}, {%4,%5,%6,%7}, {%8,%9}, {%0,%1,%2,%3};"                  \
        : "+f"((C)[0]), "+f"((C)[1]), "+f"((C)[2]), "+f"((C)[3])                  \
        : "r"((A)[0]), "r"((A)[1]), "r"((A)[2]), "r"((A)[3]),                     \
          "r"((B)[0]), "r"((B)[1]))

// fp16-accumulate MMA for the small split-product terms (full-rate pipe)
#define MMA_H16(D, A, B)                                                         \
    asm volatile("mma.sync.aligned.m16n8k16.row.col.f16.f16.f16.f16 "            \
        "{%0,%1}, {%2,%3,%4,%5}, {%6,%7}, {%0,%1};"                              \
        : "+r"((D)[0]), "+r"((D)[1])                                             \
        : "r"((A)[0]), "r"((A)[1]), "r"((A)[2]), "r"((A)[3]),                     \
          "r"((B)[0]), "r"((B)[1]))

__device__ __forceinline__ void split_f16(float v, __half& h, __half& l)
{
    h = __float2half_rn(v);
    l = __float2half_rn(v - __half2float(h));
}

// ---------------- merged prepass ----------------
__device__ __forceinline__ void prep_one(const float* __restrict__ w,
                                         __half* __restrict__ oh, __half* __restrict__ ol,
                                         int total, int Cout, int Cin, int KS, int idx)
{
    if (idx >= total) return;
    int per_layer = Cout * Cin * KS;
    int layer = idx / per_layer;
    int r = idx - layer * per_layer;
    int co = r / (Cin * KS);
    int r2 = r - co * (Cin * KS);
    int ci = r2 / KS;
    int tap = r2 - ci * KS;
    __half h, l;
    split_f16(w[idx], h, l);
    int kidx = (ci >> 4) * (16 * KS) + tap * 16 + (ci & 15);
    size_t o = ((size_t)layer * Cout + co) * (size_t)(Cin * KS) + kidx;
    oh[o] = h; ol[o] = l;
}

__global__ void prep_all(
    const float* __restrict__ x,
    const float* __restrict__ cinw, const float* __restrict__ e1,
    const float* __restrict__ e2,  const float* __restrict__ ep,
    const float* __restrict__ p1,  const float* __restrict__ p2,
    const float* __restrict__ pp,  const float* __restrict__ pi,
    const float* __restrict__ po,
    __half* __restrict__ wh, __half* __restrict__ wl,
    __half* __restrict__ xh, __half* __restrict__ xl)
{
    int idx = blockIdx.x * 256 + threadIdx.x;
    switch (blockIdx.y) {
    case 0:
        if (idx < (int)WSZ_CIN) {
            int co = idx / CINP, ci = idx - co * CINP;
            float v = (ci < 80) ? cinw[co * 80 + ci] : 0.f;
            __half h, l;
            split_f16(v, h, l);
            wh[OW_CIN + idx] = h; wl[OW_CIN + idx] = l;
        }
        break;
    case 1: prep_one(e1, wh + OW_E1, wl + OW_E1, (int)WSZ_E1, HH2, HH, 3, idx); break;
    case 2: prep_one(e2, wh + OW_E2, wl + OW_E2, (int)WSZ_E2, HH, HH2, 1, idx); break;
    case 3: prep_one(ep, wh + OW_EP, wl + OW_EP, (int)WSZ_EP, HH, HH, 3, idx); break;
    case 4: prep_one(p1, wh + OW_P1, wl + OW_P1, (int)WSZ_E1, HH2, HH, 3, idx); break;
    case 5: prep_one(p2, wh + OW_P2, wl + OW_P2, (int)WSZ_E2, HH, HH2, 1, idx); break;
    case 6: prep_one(pp, wh + OW_PP, wl + OW_PP, (int)WSZ_EP, HH, HH, 3, idx); break;
    case 7: prep_one(pi, wh + OW_PI, wl + OW_PI, (int)WSZ_PI, CVQd, HH, 1, idx); break;
    case 8: prep_one(po, wh + OW_PO, wl + OW_PO, (int)WSZ_PO, HH, CVQd, 1, idx); break;
    default:
        if (idx < (int)SZ_XP) {
            int b = idx / (CINP * TT);
            int r = idx - b * CINP * TT;
            int t = r / CINP, c = r - t * CINP;
            float v = (c < 80) ? x[((size_t)b * 80 + c) * TT + t] : 0.f;
            __half h, l;
            split_f16(v, h, l);
            size_t o = ((size_t)b * TT + t) * CINP + c;
            xh[o] = h; xl[o] = l;
        }
        break;
    }
}

// ---------------- LayerNorm (t-major): warp per row ----------------
__global__ void ln_kernel(const float* __restrict__ in, __half* __restrict__ outh,
                          __half* __restrict__ outl,
                          const float* __restrict__ gma, const float* __restrict__ bta,
                          const float* __restrict__ mask, int Tdim)
{
    int row = blockIdx.x * 8 + (threadIdx.x >> 5);
    if (row >= BB * Tdim) return;
    int lane = threadIdx.x & 31;
    const float4* p = (const float4*)(in + (size_t)row * HH) + lane * 2;
    float4 a = p[0], q = p[1];
    float v[8] = {a.x, a.y, a.z, a.w, q.x, q.y, q.z, q.w};
    float s = 0.f, s2 = 0.f;
    #pragma unroll
    for (int i = 0; i < 8; i++) { s += v[i]; s2 += v[i] * v[i]; }
    #pragma unroll
    for (int o = 16; o; o >>= 1) {
        s  += __shfl_xor_sync(0xffffffffu, s, o);
        s2 += __shfl_xor_sync(0xffffffffu, s2, o);
    }
    float mean = s * (1.f / HH);
    float var  = s2 * (1.f / HH) - mean * mean;
    float r = rsqrtf(var + 1e-5f);
    float mk = mask ? mask[row] : 1.f;
    __half2 hv[4], lv[4];
    #pragma unroll
    for (int i = 0; i < 4; i++) {
        int c = lane * 8 + 2 * i;
        float n0 = ((v[2*i]   - mean) * r * gma[c]     + bta[c])     * mk;
        float n1 = ((v[2*i+1] - mean) * r * gma[c + 1] + bta[c + 1]) * mk;
        __half h0, l0, h1, l1;
        split_f16(n0, h0, l0);
        split_f16(n1, h1, l1);
        hv[i] = __halves2half2(h0, h1);
        lv[i] = __halves2half2(l0, l1);
    }
    *(uint4*)(outh + (size_t)row * HH + lane * 8) = *(uint4*)hv;
    *(uint4*)(outl + (size_t)row * HH + lane * 8) = *(uint4*)lv;
}

// ---------------- fp16-split mma.sync conv GEMM ----------------
// h-product -> fp32-acc MMA; the two small l-products -> shared fp16-acc MMA chain.
// KS=3: 4-buffer pipeline (distance 3); KS=1: 3-buffer (distance 2).
template<int KS>
__global__ void __launch_bounds__(256, 2)
mma_conv(const __half* __restrict__ inh, const __half* __restrict__ inl,
         const __half* __restrict__ wh, const __half* __restrict__ wl,
         const float* __restrict__ bias,
         float* outF, int tmaj, __half* outH, __half* outL,
         const float* __restrict__ residual, const float* __restrict__ mask,
         int Cin, int Cout, int Tdim, float scale, int dogelu)
{
    extern __shared__ char smc[];
    constexpr int SXX = (KS == 3) ? 24 : 40;
    constexpr int SXW = (KS == 3) ? 56 : 40;
    constexpr int XPL = (KS == 3) ? 132 * 24 : 128 * 40;
    constexpr int WPL = 64 * SXW;
    constexpr int BUF = 2 * (XPL + WPL);
    constexpr int NBUF = (KS == 3) ? 4 : 3;

    const int b   = blockIdx.z;
    const int cog = blockIdx.y * 64;
    const int tg  = blockIdx.x * 128;
    const int tid = threadIdx.x;
    const int lane = tid & 31, wid = tid >> 5;
    const int wm = wid >> 2, wn = wid & 3;
    const int g = lane >> 2, th = lane & 3;

    const uint32_t smb = smem_to_u32(smc);
    const int Ktot = Cin * KS;
    const size_t xb = (size_t)b * Tdim * Cin;

    const int laneA = ((lane & 7) + ((lane >> 3) & 1) * 8) * SXW + (lane >> 4) * 8;
    const int laneB = ((lane & 7) + (lane >> 4) * 8) * SXX + ((lane >> 3) & 1) * 8;

    float c[2][4][4];
    uint32_t d[2][4][2];   // fp16 accumulators for l-products
    #pragma unroll
    for (int i = 0; i < 2; i++)
        #pragma unroll
        for (int j = 0; j < 4; j++) {
            #pragma unroll
            for (int k = 0; k < 4; k++) c[i][j][k] = 0.f;
            d[i][j][0] = 0u; d[i][j][1] = 0u;
        }

    const int nst = (KS == 3) ? (Cin >> 4) : (Cin >> 5);

    auto load_stage = [&](int s, int buf) {
        const uint32_t bb = smb + 2u * (uint32_t)(buf * BUF);
        if (KS == 3) {
            const int ci0 = s * 16;
            #pragma unroll
            for (int it = 0; it < 3; it++) {
                int ic = it * 256 + tid;
                int plane = (ic >= 384) ? 1 : 0;
                int r = ic - plane * 384;
                int row = r / 6, ch = r - row * 6;
                const __half* src = (plane ? wl : wh) + (size_t)(cog + row) * Ktot + s * 48 + ch * 8;
                CP16A(bb + 2u * (uint32_t)(2 * XPL + plane * WPL + row * SXW + ch * 8), src);
            }
            #pragma unroll
            for (int it = 0; it < 3; it++) {
                int ic = it * 256 + tid;
                if (ic < 520) {
                    int plane = (ic >= 260) ? 1 : 0;
                    int r = ic - plane * 260;
                    int u = r >> 1, ch = r & 1;
                    int gt = tg - 2 + u;
                    const __half* src = (plane ? inl : inh) + xb + (size_t)gt * Cin + ci0 + ch * 8;
                    int ssz = (gt >= 0) ? 16 : 0;
                    CP16Z(bb + 2u * (uint32_t)(plane * XPL + u * SXX + ch * 8), src, ssz);
                }
            }
        } else {
            const int ci0 = s * 32;
            #pragma unroll
            for (int it = 0; it < 2; it++) {
                int ic = it * 256 + tid;
                int plane = ic >> 8, r = ic & 255;
                int row = r >> 2, ch = r & 3;
                const __half* src = (plane ? wl : wh) + (size_t)(cog + row) * Ktot + ci0 + ch * 8;
                CP16A(bb + 2u * (uint32_t)(2 * XPL + plane * WPL + row * SXW + ch * 8), src);
            }
            #pragma unroll
            for (int it = 0; it < 4; it++) {
                int ic = it * 256 + tid;
                int plane = ic >> 9, r = ic & 511;
                int t = r >> 2, ch = r & 3;
                const __half* src = (plane ? inl : inh) + xb + (size_t)(tg + t) * Cin + ci0 + ch * 8;
                CP16(bb + 2u * (uint32_t)(plane * XPL + t * SXX + ch * 8), src);
            }
        }
    };

    auto compute_ks = [&](int buf, int ks) {
        const uint32_t bb = smb + 2u * (uint32_t)(buf * BUF);
        uint32_t ah[2][4], al[2][4];
        #pragma unroll
        for (int mf = 0; mf < 2; mf++) {
            uint32_t base = bb + 2u * (uint32_t)(2 * XPL + (wm * 32 + mf * 16) * SXW + ks * 16 + laneA);
            LDSM4(ah[mf][0], ah[mf][1], ah[mf][2], ah[mf][3], base);
            LDSM4(al[mf][0], al[mf][1], al[mf][2], al[mf][3], base + 2u * (uint32_t)WPL);
        }
        #pragma unroll
        for (int p = 0; p < 2; p++) {
            uint32_t bh[2][2], bl[2][2];
            int rowb = wn * 32 + p * 16 + ((KS == 3) ? ks : 0);
            int colb = (KS == 3) ? 0 : ks * 16;
            uint32_t base = bb + 2u * (uint32_t)(rowb * SXX + colb + laneB);
            LDSM4(bh[0][0], bh[0][1], bh[1][0], bh[1][1], base);
            LDSM4(bl[0][0], bl[0][1], bl[1][0], bl[1][1], base + 2u * (uint32_t)XPL);
            // h-product: fp32 accumulate
            #pragma unroll
            for (int mf = 0; mf < 2; mf++)
                #pragma unroll
                for (int q = 0; q < 2; q++)
                    MMA_F16(c[mf][2*p+q], ah[mf], bh[q]);
            // l-products: fp16 accumulate (both into the same d chain)
            #pragma unroll
            for (int mf = 0; mf < 2; mf++)
                #pragma unroll
                for (int q = 0; q < 2; q++)
                    MMA_H16(d[mf][2*p+q], ah[mf], bl[q]);
            #pragma unroll
            for (int mf = 0; mf < 2; mf++)
                #pragma unroll
                for (int q = 0; q < 2; q++)
                    MMA_H16(d[mf][2*p+q], al[mf], bh[q]);
        }
    };

    // ---- pipelined mainloop (prefetch distance NBUF-1, loads after kstep0) ----
    {
        int pre = (nst < NBUF - 1) ? nst : (NBUF - 1);
        for (int p = 0; p < pre; p++) {
            load_stage(p, p);
            asm volatile("cp.async.commit_group;");
        }
    }
    for (int s = 0; s < nst; s++) {
        if (KS == 3) {
            if (s + 2 < nst)      asm volatile("cp.async.wait_group 2;");
            else if (s + 1 < nst) asm volatile("cp.async.wait_group 1;");
            else                  asm volatile("cp.async.wait_group 0;");
        } else {
            if (s + 1 < nst)      asm volatile("cp.async.wait_group 1;");
            else                  asm volatile("cp.async.wait_group 0;");
        }
        __syncthreads();
        int buf = s % NBUF;
        compute_ks(buf, 0);
        if (s + NBUF - 1 < nst) {
            load_stage(s + NBUF - 1, (s + NBUF - 1) % NBUF);
            asm volatile("cp.async.commit_group;");
        }
        if (KS == 3) { compute_ks(buf, 1); compute_ks(buf, 2); }
        else         { compute_ks(buf, 1); }
    }

    // ---- epilogue: combine fp32 + fp16 accumulators ----
    #pragma unroll
    for (int mf = 0; mf < 2; mf++) {
        #pragma unroll
        for (int nf = 0; nf < 4; nf++) {
            float2 dl0 = __half22float2(*(__half2*)&d[mf][nf][0]);
            float2 dl1 = __half22float2(*(__half2*)&d[mf][nf][1]);
            c[mf][nf][0] += dl0.x; c[mf][nf][1] += dl0.y;
            c[mf][nf][2] += dl1.x; c[mf][nf][3] += dl1.y;

            int co0 = cog + wm * 32 + mf * 16 + g;
            int t0 = tg + wn * 32 + nf * 8 + 2 * th;
            float mk0 = mask ? mask[b * Tdim + t0] : 1.f;
            float mk1 = mask ? mask[b * Tdim + t0 + 1] : 1.f;
            #pragma unroll
            for (int half = 0; half < 2; half++) {
                int co = co0 + half * 8;
                float bi = bias[co];
                float v0 = (c[mf][nf][half * 2 + 0] + bi) * scale;
                float v1 = (c[mf][nf][half * 2 + 1] + bi) * scale;
                if (dogelu) {
                    v0 = 0.5f * v0 * (1.f + erff(v0 * 0.70710678118654752f));
                    v1 = 0.5f * v1 * (1.f + erff(v1 * 0.70710678118654752f));
                }
                size_t r0 = ((size_t)b * Tdim + t0) * Cout + co;
                size_t r1 = r0 + Cout;
                if (residual) { v0 += residual[r0]; v1 += residual[r1]; }
                if (mask) { v0 *= mk0; v1 *= mk1; }
                if (outF) {
                    if (tmaj) { outF[r0] = v0; outF[r1] = v1; }
                    else {
                        size_t o = ((size_t)b * Cout + co) * Tdim + t0;
                        outF[o] = v0; outF[o + 1] = v1;
                    }
                }
                if (outH) {
                    __half h0, l0, h1, l1;
                    split_f16(v0, h0, l0);
                    split_f16(v1, h1, l1);
                    outH[r0] = h0; outH[r1] = h1;
                    outL[r0] = l0; outL[r1] = l1;
                }
            }
        }
    }
}

// ---------------- group_by_segs (t-major) ----------------
__global__ void seg_zero(float* seg, float* cnt)
{
    int i = blockIdx.x * blockDim.x + threadIdx.x;
    if (i < (int)SZ_SEG) seg[i] = 0.f;
    if (i < (int)SZ_CNT) cnt[i] = 0.f;
}
__global__ void seg_scatter(const float* __restrict__ in, const int* __restrict__ mel2ph,
                            float* seg, float* cnt)
{
    int t = blockIdx.x, b = blockIdx.y, c = threadIdx.x;
    int ph = mel2ph[b * TT + t];
    if (ph < 1 || ph > LL) return;
    float v = in[((size_t)b * TT + t) * HH + c];
    atomicAdd(&seg[((size_t)b * (LL + 1) + ph) * HH + c], v);
    if (c == 0) atomicAdd(&cnt[b * (LL + 1) + ph], 1.f);
}
__global__ void seg_div(const float* __restrict__ seg, const float* __restrict__ cnt,
                        float* __restrict__ outg)
{
    int i = blockIdx.x * blockDim.x + threadIdx.x;
    if (i >= BB * LL * HH) return;
    int c = i % HH; int bl = i / HH; int l = bl % LL; int b = bl / LL;
    float s = seg[((size_t)b * (LL + 1) + l + 1) * HH + c];
    float n = fmaxf(cnt[b * (LL + 1) + l + 1], 1.f);
    outg[i] = s / n;
}

// ---------------- VQ (t-major) ----------------
__global__ void loss_init(float* loss) { if (threadIdx.x == 0) *loss = 0.f; }

__global__ void vq_kernel(const float* __restrict__ z, const float* __restrict__ cb,
                          __half* __restrict__ qh, __half* __restrict__ ql,
                          float* __restrict__ outIdx, float* loss)
{
    __shared__ float zsh[64];
    __shared__ float dsh[128];
    __shared__ int   ish[128];
    int l = blockIdx.x, b = blockIdx.y, tid = threadIdx.x;
    if (tid < 64) zsh[tid] = z[((size_t)b * LL + l) * CVQd + tid];
    __syncthreads();
    float x2 = 0.f, dot = 0.f, c2 = 0.f;
    #pragma unroll 8
    for (int c = 0; c < 64; c++) {
        float zv = zsh[c]; float cv = cb[tid * 64 + c];
        x2 += zv * zv; dot += zv * cv; c2 += cv * cv;
    }
    dsh[tid] = x2 - 2.f * dot + c2;
    ish[tid] = tid;
    __syncthreads();
    for (int s = 64; s > 0; s >>= 1) {
        if (tid < s) {
            float d2 = dsh[tid + s]; int i2 = ish[tid + s];
            if (d2 < dsh[tid] || (d2 == dsh[tid] && i2 < ish[tid])) { dsh[tid] = d2; ish[tid] = i2; }
        }
        __syncthreads();
    }
    int best = ish[0];
    __syncthreads();
    float part = 0.f;
    if (tid < 64) {
        float qv = cb[best * 64 + tid];
        size_t oi = ((size_t)b * LL + l) * CVQd + tid;
        __half h, lo;
        split_f16(qv, h, lo);
        qh[oi] = h; ql[oi] = lo;
        float dd = zsh[tid] - qv;
        part = dd * dd;
    }
    dsh[tid] = part;
    __syncthreads();
    for (int s = 64; s > 0; s >>= 1) { if (tid < s) dsh[tid] += dsh[tid + s]; __syncthreads(); }
    if (tid == 0) {
        atomicAdd(loss, dsh[0]);
        outIdx[b * LL + l] = (float)best;
    }
}

__global__ void loss_fin(const float* loss, float* out)
{
    out[0] = loss[0] * 0.25f / (float)(BB * LL * CVQd);
}

// ---------------- launch ----------------
extern "C" void kernel_launch(void* const* d_in, const int* in_sizes, int n_in,
                              void* d_out, int out_size)
{
    float* scratch = nullptr;
    cudaGetSymbolAddress((void**)&scratch, g_scratch);
    float*  bx  = scratch + O_BX;
    float*  by  = scratch + O_BY;
    __half* bnh = (__half*)(scratch + O_BNH);
    __half* bnl = (__half*)(scratch + O_BNL);
    __half* bmh = (__half*)(scratch + O_BMH);
    __half* bml = (__half*)(scratch + O_BML);
    __half* xh  = (__half*)(scratch + O_XH);
    __half* xl  = (__half*)(scratch + O_XL);
    __half* byh = (__half*)(scratch + O_BYH);
    __half* byl = (__half*)(scratch + O_BYL);
    float*  seg = scratch + O_SEG;
    float*  cnt = scratch + O_CNT;
    float*  bz  = scratch + O_BZ;
    __half* qh  = (__half*)(scratch + O_QH);
    __half* ql  = (__half*)(scratch + O_QL);
    float*  loss = scratch + O_LOSS;
    __half* wh  = (__half*)(scratch + O_WH);
    __half* wl  = (__half*)(scratch + O_WL);

    const float* x        = (const float*)d_in[0];
    const float* in_mask  = (const float*)d_in[1];
    const int*   mel2ph   = (const int*)  d_in[2];
    const float* ph_mask  = (const float*)d_in[3];
    const float* conv_in_w = (const float*)d_in[4];
    const float* conv_in_b = (const float*)d_in[5];
    const float* enc_ln_g = (const float*)d_in[6];
    const float* enc_ln_b = (const float*)d_in[7];
    const float* enc_w1   = (const float*)d_in[8];
    const float* enc_b1   = (const float*)d_in[9];
    const float* enc_w2   = (const float*)d_in[10];
    const float* enc_b2   = (const float*)d_in[11];
    const float* enc_last_g = (const float*)d_in[12];
    const float* enc_last_b = (const float*)d_in[13];
    const float* enc_post_w = (const float*)d_in[14];
    const float* enc_post_b = (const float*)d_in[15];
    const float* pn_ln_g = (const float*)d_in[16];
    const float* pn_ln_b = (const float*)d_in[17];
    const float* pn_w1   = (const float*)d_in[18];
    const float* pn_b1   = (const float*)d_in[19];
    const float* pn_w2   = (const float*)d_in[20];
    const float* pn_b2   = (const float*)d_in[21];
    const float* pn_last_g = (const float*)d_in[22];
    const float* pn_last_b = (const float*)d_in[23];
    const float* pn_post_w = (const float*)d_in[24];
    const float* pn_post_b = (const float*)d_in[25];
    const float* proj_in_w  = (const float*)d_in[26];
    const float* proj_in_b  = (const float*)d_in[27];
    const float* proj_out_w = (const float*)d_in[28];
    const float* proj_out_b = (const float*)d_in[29];
    const float* codebook   = (const float*)d_in[30];

    float* out = (float*)d_out;
    const float scale = 0.57735026918962576f;   // 3^-0.5

    const int SM3 = 4 * 2 * (132 * 24 + 64 * 56) * 2;
    const int SM1 = 3 * 2 * (128 * 40 + 64 * 40) * 2;
    cudaFuncSetAttribute(mma_conv<3>, cudaFuncAttributeMaxDynamicSharedMemorySize, SM3);
    cudaFuncSetAttribute(mma_conv<1>, cudaFuncAttributeMaxDynamicSharedMemorySize, SM1);

    dim3 blk(256);

    // ---- prepass (single launch) + early independent zero/init ----
    prep_all<<<dim3(15360, 10), 256>>>(x, conv_in_w, enc_w1, enc_w2, enc_post_w,
                                       pn_w1, pn_w2, pn_post_w, proj_in_w, proj_out_w,
                                       wh, wl, xh, xl);
    seg_zero<<<((int)SZ_SEG + 255)/256, 256>>>(seg, cnt);
    loss_init<<<1, 32>>>(loss);

    // ---- encoder (T = TT) ----
    mma_conv<1><<<dim3(TT/128, HH/64, BB), blk, SM1>>>(xh, xl, wh + OW_CIN, wl + OW_CIN,
        conv_in_b, bx, 1, nullptr, nullptr, nullptr, in_mask, CINP, HH, TT, 1.f, 0);
    for (int i = 0; i < NLB; i++) {
        ln_kernel<<<(BB*TT)/8, 256>>>(bx, bnh, bnl,
            enc_ln_g + i*HH, enc_ln_b + i*HH, nullptr, TT);
        mma_conv<3><<<dim3(TT/128, HH2/64, BB), blk, SM3>>>(bnh, bnl,
            wh + OW_E1 + (size_t)i*HH2*HH*3, wl + OW_E1 + (size_t)i*HH2*HH*3,
            enc_b1 + i*HH2, nullptr, 0, bmh, bml, nullptr, nullptr, HH, HH2, TT, scale, 1);
        mma_conv<1><<<dim3(TT/128, HH/64, BB), blk, SM1>>>(bmh, bml,
            wh + OW_E2 + (size_t)i*HH*HH2, wl + OW_E2 + (size_t)i*HH*HH2,
            enc_b2 + i*HH, bx, 1, nullptr, nullptr, bx, in_mask, HH2, HH, TT, 1.f, 0);
    }
    ln_kernel<<<(BB*TT)/8, 256>>>(bx, bnh, bnl, enc_last_g, enc_last_b, in_mask, TT);
    mma_conv<3><<<dim3(TT/128, HH/64, BB), blk, SM3>>>(bnh, bnl, wh + OW_EP, wl + OW_EP,
        enc_post_b, by, 1, nullptr, nullptr, nullptr, in_mask, HH, HH, TT, 1.f, 0);

    // ---- group by segments -> [b][l][c] into bx ----
    seg_scatter<<<dim3(TT, BB), HH>>>(by, mel2ph, seg, cnt);
    seg_div<<<(BB*LL*HH + 255)/256, 256>>>(seg, cnt, bx);

    // ---- postnet (T = LL) ----
    for (int i = 0; i < NLB; i++) {
        ln_kernel<<<(BB*LL)/8, 256>>>(bx, bnh, bnl,
            pn_ln_g + i*HH, pn_ln_b + i*HH, nullptr, LL);
        mma_conv<3><<<dim3(LL/128, HH2/64, BB), blk, SM3>>>(bnh, bnl,
            wh + OW_P1 + (size_t)i*HH2*HH*3, wl + OW_P1 + (size_t)i*HH2*HH*3,
            pn_b1 + i*HH2, nullptr, 0, bmh, bml, nullptr, nullptr, HH, HH2, LL, scale, 1);
        mma_conv<1><<<dim3(LL/128, HH/64, BB), blk, SM1>>>(bmh, bml,
            wh + OW_P2 + (size_t)i*HH*HH2, wl + OW_P2 + (size_t)i*HH*HH2,
            pn_b2 + i*HH, bx, 1, nullptr, nullptr, bx, ph_mask, HH2, HH, LL, 1.f, 0);
    }
    ln_kernel<<<(BB*LL)/8, 256>>>(bx, bnh, bnl, pn_last_g, pn_last_b, ph_mask, LL);
    mma_conv<3><<<dim3(LL/128, HH/64, BB), blk, SM3>>>(bnh, bnl, wh + OW_PP, wl + OW_PP,
        pn_post_b, nullptr, 0, byh, byl, nullptr, ph_mask, HH, HH, LL, 1.f, 0);

    // ---- proj_in -> VQ -> proj_out ----
    mma_conv<1><<<dim3(LL/128, 1, BB), blk, SM1>>>(byh, byl, wh + OW_PI, wl + OW_PI,
        proj_in_b, bz, 1, nullptr, nullptr, nullptr, nullptr, HH, CVQd, LL, 1.f, 0);
    vq_kernel<<<dim3(LL, BB), 128>>>(bz, codebook, qh, ql, out + (size_t)BB*HH*LL + 1, loss);
    mma_conv<1><<<dim3(LL/128, HH/64, BB), blk, SM1>>>(qh, ql, wh + OW_PO, wl + OW_PO,
        proj_out_b, out, 0, nullptr, nullptr, nullptr, nullptr, CVQd, HH, LL, 1.f, 0);
    loss_fin<<<1, 1>>>(loss, out + (size_t)BB*HH*LL);
}

// round 17
// speedup vs baseline: 1.1652x; 1.0165x over previous
#include <cuda_runtime.h>
#include <cuda_fp16.h>
#include <math.h>
#include <stdint.h>

// ---------------- problem constants ----------------
#define BB   16
#define TT   2048
#define LL   512
#define HH   256
#define HH2  512
#define CVQd 64
#define NLB  10   // NL * NB
#define CINP 96   // conv_in padded channels (80 -> 96)

// ---------------- sizes (floats) ----------------
#define SZ_BHT  ((size_t)BB*HH*TT)
#define SZ_BMT  ((size_t)BB*HH2*TT)
#define SZ_XP   ((size_t)BB*CINP*TT)
#define SZ_BHL  ((size_t)BB*HH*LL)
#define SZ_SEG  ((size_t)BB*HH*(LL+1))
#define SZ_CNT  ((size_t)BB*(LL+1))
#define SZ_BZL  ((size_t)BB*CVQd*LL)

// weight plane sizes (elements)
#define WSZ_CIN ((size_t)HH*CINP)
#define WSZ_E1  ((size_t)NLB*HH2*HH*3)
#define WSZ_E2  ((size_t)NLB*HH*HH2)
#define WSZ_EP  ((size_t)HH*HH*3)
#define WSZ_PI  ((size_t)CVQd*HH)
#define WSZ_PO  ((size_t)HH*CVQd)
#define WTOT    (WSZ_CIN + 2*(WSZ_E1 + WSZ_E2 + WSZ_EP) + WSZ_PI + WSZ_PO)

// scratch offsets (float units). half planes take size/2 floats.
// ALL activation tensors are t-major: [b][t][c].
#define O_BX   ((size_t)0)
#define O_BY   (O_BX  + SZ_BHT)
#define O_BNH  (O_BY  + SZ_BHT)
#define O_BNL  (O_BNH + SZ_BHT/2)
#define O_BMH  (O_BNL + SZ_BHT/2)
#define O_BML  (O_BMH + SZ_BMT/2)
#define O_XH   (O_BML + SZ_BMT/2)
#define O_XL   (O_XH  + SZ_XP/2)
#define O_BYH  (O_XL  + SZ_XP/2)
#define O_BYL  (O_BYH + SZ_BHL/2)
#define O_SEG  (O_BYL + SZ_BHL/2)
#define O_CNT  (O_SEG + SZ_SEG)
#define O_BZ   (O_CNT + SZ_CNT)
#define O_QH   (O_BZ  + SZ_BZL)
#define O_QL   (O_QH  + SZ_BZL/2)
#define O_LOSS (O_QL  + SZ_BZL/2)
#define O_WH   (O_LOSS + 16)
#define O_WL   (O_WH  + WTOT/2)
#define SCRATCH_TOT (O_WL + WTOT/2)

__device__ __align__(16) float g_scratch[SCRATCH_TOT];

// weight offsets inside wh/wl planes (element units)
#define OW_CIN ((size_t)0)
#define OW_E1  (OW_CIN + WSZ_CIN)
#define OW_E2  (OW_E1 + WSZ_E1)
#define OW_EP  (OW_E2 + WSZ_E2)
#define OW_P1  (OW_EP + WSZ_EP)
#define OW_P2  (OW_P1 + WSZ_E1)
#define OW_PP  (OW_P2 + WSZ_E2)
#define OW_PI  (OW_PP + WSZ_EP)
#define OW_PO  (OW_PI + WSZ_PI)

// ---------------- helpers ----------------
__device__ __forceinline__ uint32_t smem_to_u32(const void* p) {
    uint32_t a;
    asm("{ .reg .u64 t; cvta.to.shared.u64 t, %1; cvt.u32.u64 %0, t; }" : "=r"(a) : "l"(p));
    return a;
}
#define CP16(dst, src) \
    asm volatile("cp.async.cg.shared.global [%0], [%1], 16;" :: "r"(dst), "l"(src))
#define CP16A(dst, src) \
    asm volatile("cp.async.ca.shared.global [%0], [%1], 16;" :: "r"(dst), "l"(src))
#define CP16Z(dst, src, ssz) \
    asm volatile("cp.async.cg.shared.global [%0], [%1], 16, %2;" :: "r"(dst), "l"(src), "r"(ssz))

#define LDSM4(r0, r1, r2, r3, addr)                                              \
    asm volatile("ldmatrix.sync.aligned.m8n8.x4.shared.b16 {%0,%1,%2,%3}, [%4];" \
        : "=r"(r0), "=r"(r1), "=r"(r2), "=r"(r3) : "r"(addr))

#define MMA_F16(C, A, B)                                                         \
    asm volatile("mma.sync.aligned.m16n8k16.row.col.f32.f16.f16.f32 "            \
        "{%0,%1,%2,%3}, {%4,%5,%6,%7}, {%8,%9}, {%0,%1,%2,%3};"                  \
        : "+f"((C)[0]), "+f"((C)[1]), "+f"((C)[2]), "+f"((C)[3])                  \
        : "r"((A)[0]), "r"((A)[1]), "r"((A)[2]), "r"((A)[3]),                     \
          "r"((B)[0]), "r"((B)[1]))

// fp16-accumulate MMA for the small split-product terms
#define MMA_H16(D, A, B)                                                         \
    asm volatile("mma.sync.aligned.m16n8k16.row.col.f16.f16.f16.f16 "            \
        "{%0,%1}, {%2,%3,%4,%5}, {%6,%7}, {%0,%1};"                              \
        : "+r"((D)[0]), "+r"((D)[1])                                             \
        : "r"((A)[0]), "r"((A)[1]), "r"((A)[2]), "r"((A)[3]),                     \
          "r"((B)[0]), "r"((B)[1]))

__device__ __forceinline__ void split_f16(float v, __half& h, __half& l)
{
    h = __float2half_rn(v);
    l = __float2half_rn(v - __half2float(h));
}

// ---------------- merged prepass ----------------
__device__ __forceinline__ void prep_one(const float* __restrict__ w,
                                         __half* __restrict__ oh, __half* __restrict__ ol,
                                         int total, int Cout, int Cin, int KS, int idx)
{
    if (idx >= total) return;
    int per_layer = Cout * Cin * KS;
    int layer = idx / per_layer;
    int r = idx - layer * per_layer;
    int co = r / (Cin * KS);
    int r2 = r - co * (Cin * KS);
    int ci = r2 / KS;
    int tap = r2 - ci * KS;
    __half h, l;
    split_f16(w[idx], h, l);
    int kidx = (ci >> 4) * (16 * KS) + tap * 16 + (ci & 15);
    size_t o = ((size_t)layer * Cout + co) * (size_t)(Cin * KS) + kidx;
    oh[o] = h; ol[o] = l;
}

__global__ void prep_all(
    const float* __restrict__ x,
    const float* __restrict__ cinw, const float* __restrict__ e1,
    const float* __restrict__ e2,  const float* __restrict__ ep,
    const float* __restrict__ p1,  const float* __restrict__ p2,
    const float* __restrict__ pp,  const float* __restrict__ pi,
    const float* __restrict__ po,
    __half* __restrict__ wh, __half* __restrict__ wl,
    __half* __restrict__ xh, __half* __restrict__ xl)
{
    int idx = blockIdx.x * 256 + threadIdx.x;
    switch (blockIdx.y) {
    case 0:
        if (idx < (int)WSZ_CIN) {
            int co = idx / CINP, ci = idx - co * CINP;
            float v = (ci < 80) ? cinw[co * 80 + ci] : 0.f;
            __half h, l;
            split_f16(v, h, l);
            wh[OW_CIN + idx] = h; wl[OW_CIN + idx] = l;
        }
        break;
    case 1: prep_one(e1, wh + OW_E1, wl + OW_E1, (int)WSZ_E1, HH2, HH, 3, idx); break;
    case 2: prep_one(e2, wh + OW_E2, wl + OW_E2, (int)WSZ_E2, HH, HH2, 1, idx); break;
    case 3: prep_one(ep, wh + OW_EP, wl + OW_EP, (int)WSZ_EP, HH, HH, 3, idx); break;
    case 4: prep_one(p1, wh + OW_P1, wl + OW_P1, (int)WSZ_E1, HH2, HH, 3, idx); break;
    case 5: prep_one(p2, wh + OW_P2, wl + OW_P2, (int)WSZ_E2, HH, HH2, 1, idx); break;
    case 6: prep_one(pp, wh + OW_PP, wl + OW_PP, (int)WSZ_EP, HH, HH, 3, idx); break;
    case 7: prep_one(pi, wh + OW_PI, wl + OW_PI, (int)WSZ_PI, CVQd, HH, 1, idx); break;
    case 8: prep_one(po, wh + OW_PO, wl + OW_PO, (int)WSZ_PO, HH, CVQd, 1, idx); break;
    default:
        if (idx < (int)SZ_XP) {
            int b = idx / (CINP * TT);
            int r = idx - b * CINP * TT;
            int t = r / CINP, c = r - t * CINP;
            float v = (c < 80) ? x[((size_t)b * 80 + c) * TT + t] : 0.f;
            __half h, l;
            split_f16(v, h, l);
            size_t o = ((size_t)b * TT + t) * CINP + c;
            xh[o] = h; xl[o] = l;
        }
        break;
    }
}

// ---------------- LayerNorm (t-major): warp per row ----------------
__global__ void ln_kernel(const float* __restrict__ in, __half* __restrict__ outh,
                          __half* __restrict__ outl,
                          const float* __restrict__ gma, const float* __restrict__ bta,
                          const float* __restrict__ mask, int Tdim)
{
    int row = blockIdx.x * 8 + (threadIdx.x >> 5);
    if (row >= BB * Tdim) return;
    int lane = threadIdx.x & 31;
    const float4* p = (const float4*)(in + (size_t)row * HH) + lane * 2;
    float4 a = p[0], q = p[1];
    float v[8] = {a.x, a.y, a.z, a.w, q.x, q.y, q.z, q.w};
    float s = 0.f, s2 = 0.f;
    #pragma unroll
    for (int i = 0; i < 8; i++) { s += v[i]; s2 += v[i] * v[i]; }
    #pragma unroll
    for (int o = 16; o; o >>= 1) {
        s  += __shfl_xor_sync(0xffffffffu, s, o);
        s2 += __shfl_xor_sync(0xffffffffu, s2, o);
    }
    float mean = s * (1.f / HH);
    float var  = s2 * (1.f / HH) - mean * mean;
    float r = rsqrtf(var + 1e-5f);
    float mk = mask ? mask[row] : 1.f;
    __half2 hv[4], lv[4];
    #pragma unroll
    for (int i = 0; i < 4; i++) {
        int c = lane * 8 + 2 * i;
        float n0 = ((v[2*i]   - mean) * r * gma[c]     + bta[c])     * mk;
        float n1 = ((v[2*i+1] - mean) * r * gma[c + 1] + bta[c + 1]) * mk;
        __half h0, l0, h1, l1;
        split_f16(n0, h0, l0);
        split_f16(n1, h1, l1);
        hv[i] = __halves2half2(h0, h1);
        lv[i] = __halves2half2(l0, l1);
    }
    *(uint4*)(outh + (size_t)row * HH + lane * 8) = *(uint4*)hv;
    *(uint4*)(outl + (size_t)row * HH + lane * 8) = *(uint4*)lv;
}

// ---------------- fp16-split mma.sync conv GEMM ----------------
// h-product -> fp32-acc MMA; the two small l-products -> shared fp16-acc chain.
// KS=3: 4-buffer pipeline (distance 3); KS=1: 3-buffer (distance 2).
// cp.async loads are spread BETWEEN ksteps to de-burst the LSU pipe.
template<int KS>
__global__ void __launch_bounds__(256, 2)
mma_conv(const __half* __restrict__ inh, const __half* __restrict__ inl,
         const __half* __restrict__ wh, const __half* __restrict__ wl,
         const float* __restrict__ bias,
         float* outF, int tmaj, __half* outH, __half* outL,
         const float* __restrict__ residual, const float* __restrict__ mask,
         int Cin, int Cout, int Tdim, float scale, int dogelu)
{
    extern __shared__ char smc[];
    constexpr int SXX = (KS == 3) ? 24 : 40;
    constexpr int SXW = (KS == 3) ? 56 : 40;
    constexpr int XPL = (KS == 3) ? 132 * 24 : 128 * 40;
    constexpr int WPL = 64 * SXW;
    constexpr int BUF = 2 * (XPL + WPL);
    constexpr int NBUF = (KS == 3) ? 4 : 3;

    const int b   = blockIdx.z;
    const int cog = blockIdx.y * 64;
    const int tg  = blockIdx.x * 128;
    const int tid = threadIdx.x;
    const int lane = tid & 31, wid = tid >> 5;
    const int wm = wid >> 2, wn = wid & 3;
    const int g = lane >> 2, th = lane & 3;

    const uint32_t smb = smem_to_u32(smc);
    const int Ktot = Cin * KS;
    const size_t xb = (size_t)b * Tdim * Cin;

    const int laneA = ((lane & 7) + ((lane >> 3) & 1) * 8) * SXW + (lane >> 4) * 8;
    const int laneB = ((lane & 7) + (lane >> 4) * 8) * SXX + ((lane >> 3) & 1) * 8;

    float c[2][4][4];
    uint32_t d[2][4][2];
    #pragma unroll
    for (int i = 0; i < 2; i++)
        #pragma unroll
        for (int j = 0; j < 4; j++) {
            #pragma unroll
            for (int k = 0; k < 4; k++) c[i][j][k] = 0.f;
            d[i][j][0] = 0u; d[i][j][1] = 0u;
        }

    const int nst = (KS == 3) ? (Cin >> 4) : (Cin >> 5);

    // ---- load fragments ----
    auto load_w = [&](int s, int buf) {
        const uint32_t bb = smb + 2u * (uint32_t)(buf * BUF);
        if (KS == 3) {
            #pragma unroll
            for (int it = 0; it < 3; it++) {
                int ic = it * 256 + tid;
                int plane = (ic >= 384) ? 1 : 0;
                int r = ic - plane * 384;
                int row = r / 6, ch = r - row * 6;
                const __half* src = (plane ? wl : wh) + (size_t)(cog + row) * Ktot + s * 48 + ch * 8;
                CP16A(bb + 2u * (uint32_t)(2 * XPL + plane * WPL + row * SXW + ch * 8), src);
            }
        } else {
            const int ci0 = s * 32;
            #pragma unroll
            for (int it = 0; it < 2; it++) {
                int ic = it * 256 + tid;
                int plane = ic >> 8, r = ic & 255;
                int row = r >> 2, ch = r & 3;
                const __half* src = (plane ? wl : wh) + (size_t)(cog + row) * Ktot + ci0 + ch * 8;
                CP16A(bb + 2u * (uint32_t)(2 * XPL + plane * WPL + row * SXW + ch * 8), src);
            }
        }
    };
    auto load_x = [&](int s, int buf, int part) {   // part used only for KS==1
        const uint32_t bb = smb + 2u * (uint32_t)(buf * BUF);
        if (KS == 3) {
            const int ci0 = s * 16;
            #pragma unroll
            for (int it = 0; it < 3; it++) {
                int ic = it * 256 + tid;
                if (ic < 520) {
                    int plane = (ic >= 260) ? 1 : 0;
                    int r = ic - plane * 260;
                    int u = r >> 1, ch = r & 1;
                    int gt = tg - 2 + u;
                    const __half* src = (plane ? inl : inh) + xb + (size_t)gt * Cin + ci0 + ch * 8;
                    int ssz = (gt >= 0) ? 16 : 0;
                    CP16Z(bb + 2u * (uint32_t)(plane * XPL + u * SXX + ch * 8), src, ssz);
                }
            }
        } else {
            const int ci0 = s * 32;
            #pragma unroll
            for (int it = 0; it < 2; it++) {
                int ic = (part * 2 + it) * 256 + tid;
                int plane = ic >> 9, r = ic & 511;
                int t = r >> 2, ch = r & 3;
                const __half* src = (plane ? inl : inh) + xb + (size_t)(tg + t) * Cin + ci0 + ch * 8;
                CP16(bb + 2u * (uint32_t)(plane * XPL + t * SXX + ch * 8), src);
            }
        }
    };
    auto load_all = [&](int s, int buf) {
        load_w(s, buf);
        load_x(s, buf, 0);
        if (KS == 1) load_x(s, buf, 1);
    };

    auto compute_ks = [&](int buf, int ks) {
        const uint32_t bb = smb + 2u * (uint32_t)(buf * BUF);
        uint32_t ah[2][4], al[2][4];
        #pragma unroll
        for (int mf = 0; mf < 2; mf++) {
            uint32_t base = bb + 2u * (uint32_t)(2 * XPL + (wm * 32 + mf * 16) * SXW + ks * 16 + laneA);
            LDSM4(ah[mf][0], ah[mf][1], ah[mf][2], ah[mf][3], base);
            LDSM4(al[mf][0], al[mf][1], al[mf][2], al[mf][3], base + 2u * (uint32_t)WPL);
        }
        #pragma unroll
        for (int p = 0; p < 2; p++) {
            uint32_t bh[2][2], bl[2][2];
            int rowb = wn * 32 + p * 16 + ((KS == 3) ? ks : 0);
            int colb = (KS == 3) ? 0 : ks * 16;
            uint32_t base = bb + 2u * (uint32_t)(rowb * SXX + colb + laneB);
            LDSM4(bh[0][0], bh[0][1], bh[1][0], bh[1][1], base);
            LDSM4(bl[0][0], bl[0][1], bl[1][0], bl[1][1], base + 2u * (uint32_t)XPL);
            #pragma unroll
            for (int mf = 0; mf < 2; mf++)
                #pragma unroll
                for (int q = 0; q < 2; q++)
                    MMA_F16(c[mf][2*p+q], ah[mf], bh[q]);
            #pragma unroll
            for (int mf = 0; mf < 2; mf++)
                #pragma unroll
                for (int q = 0; q < 2; q++)
                    MMA_H16(d[mf][2*p+q], ah[mf], bl[q]);
            #pragma unroll
            for (int mf = 0; mf < 2; mf++)
                #pragma unroll
                for (int q = 0; q < 2; q++)
                    MMA_H16(d[mf][2*p+q], al[mf], bh[q]);
        }
    };

    // ---- pipelined mainloop (prefetch distance NBUF-1, loads spread over ksteps) ----
    {
        int pre = (nst < NBUF - 1) ? nst : (NBUF - 1);
        for (int p = 0; p < pre; p++) {
            load_all(p, p);
            asm volatile("cp.async.commit_group;");
        }
    }
    for (int s = 0; s < nst; s++) {
        if (KS == 3) {
            if (s + 2 < nst)      asm volatile("cp.async.wait_group 2;");
            else if (s + 1 < nst) asm volatile("cp.async.wait_group 1;");
            else                  asm volatile("cp.async.wait_group 0;");
        } else {
            if (s + 1 < nst)      asm volatile("cp.async.wait_group 1;");
            else                  asm volatile("cp.async.wait_group 0;");
        }
        __syncthreads();
        int buf = s % NBUF;
        bool more = (s + NBUF - 1 < nst);
        int nbuf2 = (s + NBUF - 1) % NBUF;
        if (KS == 3) {
            compute_ks(buf, 0);
            if (more) load_w(s + NBUF - 1, nbuf2);
            compute_ks(buf, 1);
            if (more) load_x(s + NBUF - 1, nbuf2, 0);
            compute_ks(buf, 2);
        } else {
            compute_ks(buf, 0);
            if (more) { load_w(s + NBUF - 1, nbuf2); load_x(s + NBUF - 1, nbuf2, 0); }
            compute_ks(buf, 1);
            if (more) load_x(s + NBUF - 1, nbuf2, 1);
        }
        if (more) asm volatile("cp.async.commit_group;");
    }

    // ---- epilogue: combine fp32 + fp16 accumulators ----
    #pragma unroll
    for (int mf = 0; mf < 2; mf++) {
        #pragma unroll
        for (int nf = 0; nf < 4; nf++) {
            float2 dl0 = __half22float2(*(__half2*)&d[mf][nf][0]);
            float2 dl1 = __half22float2(*(__half2*)&d[mf][nf][1]);
            c[mf][nf][0] += dl0.x; c[mf][nf][1] += dl0.y;
            c[mf][nf][2] += dl1.x; c[mf][nf][3] += dl1.y;

            int co0 = cog + wm * 32 + mf * 16 + g;
            int t0 = tg + wn * 32 + nf * 8 + 2 * th;
            float mk0 = mask ? mask[b * Tdim + t0] : 1.f;
            float mk1 = mask ? mask[b * Tdim + t0 + 1] : 1.f;
            #pragma unroll
            for (int half = 0; half < 2; half++) {
                int co = co0 + half * 8;
                float bi = bias[co];
                float v0 = (c[mf][nf][half * 2 + 0] + bi) * scale;
                float v1 = (c[mf][nf][half * 2 + 1] + bi) * scale;
                if (dogelu) {
                    v0 = 0.5f * v0 * (1.f + erff(v0 * 0.70710678118654752f));
                    v1 = 0.5f * v1 * (1.f + erff(v1 * 0.70710678118654752f));
                }
                size_t r0 = ((size_t)b * Tdim + t0) * Cout + co;
                size_t r1 = r0 + Cout;
                if (residual) { v0 += residual[r0]; v1 += residual[r1]; }
                if (mask) { v0 *= mk0; v1 *= mk1; }
                if (outF) {
                    if (tmaj) { outF[r0] = v0; outF[r1] = v1; }
                    else {
                        size_t o = ((size_t)b * Cout + co) * Tdim + t0;
                        outF[o] = v0; outF[o + 1] = v1;
                    }
                }
                if (outH) {
                    __half h0, l0, h1, l1;
                    split_f16(v0, h0, l0);
                    split_f16(v1, h1, l1);
                    outH[r0] = h0; outH[r1] = h1;
                    outL[r0] = l0; outL[r1] = l1;
                }
            }
        }
    }
}

// ---------------- group_by_segs (t-major) ----------------
__global__ void seg_zero(float* seg, float* cnt)
{
    int i = blockIdx.x * blockDim.x + threadIdx.x;
    if (i < (int)SZ_SEG) seg[i] = 0.f;
    if (i < (int)SZ_CNT) cnt[i] = 0.f;
}
__global__ void seg_scatter(const float* __restrict__ in, const int* __restrict__ mel2ph,
                            float* seg, float* cnt)
{
    int t = blockIdx.x, b = blockIdx.y, c = threadIdx.x;
    int ph = mel2ph[b * TT + t];
    if (ph < 1 || ph > LL) return;
    float v = in[((size_t)b * TT + t) * HH + c];
    atomicAdd(&seg[((size_t)b * (LL + 1) + ph) * HH + c], v);
    if (c == 0) atomicAdd(&cnt[b * (LL + 1) + ph], 1.f);
}
__global__ void seg_div(const float* __restrict__ seg, const float* __restrict__ cnt,
                        float* __restrict__ outg)
{
    int i = blockIdx.x * blockDim.x + threadIdx.x;
    if (i >= BB * LL * HH) return;
    int c = i % HH; int bl = i / HH; int l = bl % LL; int b = bl / LL;
    float s = seg[((size_t)b * (LL + 1) + l + 1) * HH + c];
    float n = fmaxf(cnt[b * (LL + 1) + l + 1], 1.f);
    outg[i] = s / n;
}

// ---------------- VQ (t-major) ----------------
__global__ void loss_init(float* loss) { if (threadIdx.x == 0) *loss = 0.f; }

__global__ void vq_kernel(const float* __restrict__ z, const float* __restrict__ cb,
                          __half* __restrict__ qh, __half* __restrict__ ql,
                          float* __restrict__ outIdx, float* loss)
{
    __shared__ float zsh[64];
    __shared__ float dsh[128];
    __shared__ int   ish[128];
    int l = blockIdx.x, b = blockIdx.y, tid = threadIdx.x;
    if (tid < 64) zsh[tid] = z[((size_t)b * LL + l) * CVQd + tid];
    __syncthreads();
    float x2 = 0.f, dot = 0.f, c2 = 0.f;
    #pragma unroll 8
    for (int c = 0; c < 64; c++) {
        float zv = zsh[c]; float cv = cb[tid * 64 + c];
        x2 += zv * zv; dot += zv * cv; c2 += cv * cv;
    }
    dsh[tid] = x2 - 2.f * dot + c2;
    ish[tid] = tid;
    __syncthreads();
    for (int s = 64; s > 0; s >>= 1) {
        if (tid < s) {
            float d2 = dsh[tid + s]; int i2 = ish[tid + s];
            if (d2 < dsh[tid] || (d2 == dsh[tid] && i2 < ish[tid])) { dsh[tid] = d2; ish[tid] = i2; }
        }
        __syncthreads();
    }
    int best = ish[0];
    __syncthreads();
    float part = 0.f;
    if (tid < 64) {
        float qv = cb[best * 64 + tid];
        size_t oi = ((size_t)b * LL + l) * CVQd + tid;
        __half h, lo;
        split_f16(qv, h, lo);
        qh[oi] = h; ql[oi] = lo;
        float dd = zsh[tid] - qv;
        part = dd * dd;
    }
    dsh[tid] = part;
    __syncthreads();
    for (int s = 64; s > 0; s >>= 1) { if (tid < s) dsh[tid] += dsh[tid + s]; __syncthreads(); }
    if (tid == 0) {
        atomicAdd(loss, dsh[0]);
        outIdx[b * LL + l] = (float)best;
    }
}

__global__ void loss_fin(const float* loss, float* out)
{
    out[0] = loss[0] * 0.25f / (float)(BB * LL * CVQd);
}

// ---------------- launch ----------------
extern "C" void kernel_launch(void* const* d_in, const int* in_sizes, int n_in,
                              void* d_out, int out_size)
{
    float* scratch = nullptr;
    cudaGetSymbolAddress((void**)&scratch, g_scratch);
    float*  bx  = scratch + O_BX;
    float*  by  = scratch + O_BY;
    __half* bnh = (__half*)(scratch + O_BNH);
    __half* bnl = (__half*)(scratch + O_BNL);
    __half* bmh = (__half*)(scratch + O_BMH);
    __half* bml = (__half*)(scratch + O_BML);
    __half* xh  = (__half*)(scratch + O_XH);
    __half* xl  = (__half*)(scratch + O_XL);
    __half* byh = (__half*)(scratch + O_BYH);
    __half* byl = (__half*)(scratch + O_BYL);
    float*  seg = scratch + O_SEG;
    float*  cnt = scratch + O_CNT;
    float*  bz  = scratch + O_BZ;
    __half* qh  = (__half*)(scratch + O_QH);
    __half* ql  = (__half*)(scratch + O_QL);
    float*  loss = scratch + O_LOSS;
    __half* wh  = (__half*)(scratch + O_WH);
    __half* wl  = (__half*)(scratch + O_WL);

    const float* x        = (const float*)d_in[0];
    const float* in_mask  = (const float*)d_in[1];
    const int*   mel2ph   = (const int*)  d_in[2];
    const float* ph_mask  = (const float*)d_in[3];
    const float* conv_in_w = (const float*)d_in[4];
    const float* conv_in_b = (const float*)d_in[5];
    const float* enc_ln_g = (const float*)d_in[6];
    const float* enc_ln_b = (const float*)d_in[7];
    const float* enc_w1   = (const float*)d_in[8];
    const float* enc_b1   = (const float*)d_in[9];
    const float* enc_w2   = (const float*)d_in[10];
    const float* enc_b2   = (const float*)d_in[11];
    const float* enc_last_g = (const float*)d_in[12];
    const float* enc_last_b = (const float*)d_in[13];
    const float* enc_post_w = (const float*)d_in[14];
    const float* enc_post_b = (const float*)d_in[15];
    const float* pn_ln_g = (const float*)d_in[16];
    const float* pn_ln_b = (const float*)d_in[17];
    const float* pn_w1   = (const float*)d_in[18];
    const float* pn_b1   = (const float*)d_in[19];
    const float* pn_w2   = (const float*)d_in[20];
    const float* pn_b2   = (const float*)d_in[21];
    const float* pn_last_g = (const float*)d_in[22];
    const float* pn_last_b = (const float*)d_in[23];
    const float* pn_post_w = (const float*)d_in[24];
    const float* pn_post_b = (const float*)d_in[25];
    const float* proj_in_w  = (const float*)d_in[26];
    const float* proj_in_b  = (const float*)d_in[27];
    const float* proj_out_w = (const float*)d_in[28];
    const float* proj_out_b = (const float*)d_in[29];
    const float* codebook   = (const float*)d_in[30];

    float* out = (float*)d_out;
    const float scale = 0.57735026918962576f;   // 3^-0.5

    const int SM3 = 4 * 2 * (132 * 24 + 64 * 56) * 2;
    const int SM1 = 3 * 2 * (128 * 40 + 64 * 40) * 2;
    cudaFuncSetAttribute(mma_conv<3>, cudaFuncAttributeMaxDynamicSharedMemorySize, SM3);
    cudaFuncSetAttribute(mma_conv<1>, cudaFuncAttributeMaxDynamicSharedMemorySize, SM1);

    dim3 blk(256);

    // ---- prepass (single launch) + early independent zero/init ----
    prep_all<<<dim3(15360, 10), 256>>>(x, conv_in_w, enc_w1, enc_w2, enc_post_w,
                                       pn_w1, pn_w2, pn_post_w, proj_in_w, proj_out_w,
                                       wh, wl, xh, xl);
    seg_zero<<<((int)SZ_SEG + 255)/256, 256>>>(seg, cnt);
    loss_init<<<1, 32>>>(loss);

    // ---- encoder (T = TT) ----
    mma_conv<1><<<dim3(TT/128, HH/64, BB), blk, SM1>>>(xh, xl, wh + OW_CIN, wl + OW_CIN,
        conv_in_b, bx, 1, nullptr, nullptr, nullptr, in_mask, CINP, HH, TT, 1.f, 0);
    for (int i = 0; i < NLB; i++) {
        ln_kernel<<<(BB*TT)/8, 256>>>(bx, bnh, bnl,
            enc_ln_g + i*HH, enc_ln_b + i*HH, nullptr, TT);
        mma_conv<3><<<dim3(TT/128, HH2/64, BB), blk, SM3>>>(bnh, bnl,
            wh + OW_E1 + (size_t)i*HH2*HH*3, wl + OW_E1 + (size_t)i*HH2*HH*3,
            enc_b1 + i*HH2, nullptr, 0, bmh, bml, nullptr, nullptr, HH, HH2, TT, scale, 1);
        mma_conv<1><<<dim3(TT/128, HH/64, BB), blk, SM1>>>(bmh, bml,
            wh + OW_E2 + (size_t)i*HH*HH2, wl + OW_E2 + (size_t)i*HH*HH2,
            enc_b2 + i*HH, bx, 1, nullptr, nullptr, bx, in_mask, HH2, HH, TT, 1.f, 0);
    }
    ln_kernel<<<(BB*TT)/8, 256>>>(bx, bnh, bnl, enc_last_g, enc_last_b, in_mask, TT);
    mma_conv<3><<<dim3(TT/128, HH/64, BB), blk, SM3>>>(bnh, bnl, wh + OW_EP, wl + OW_EP,
        enc_post_b, by, 1, nullptr, nullptr, nullptr, in_mask, HH, HH, TT, 1.f, 0);

    // ---- group by segments -> [b][l][c] into bx ----
    seg_scatter<<<dim3(TT, BB), HH>>>(by, mel2ph, seg, cnt);
    seg_div<<<(BB*LL*HH + 255)/256, 256>>>(seg, cnt, bx);

    // ---- postnet (T = LL) ----
    for (int i = 0; i < NLB; i++) {
        ln_kernel<<<(BB*LL)/8, 256>>>(bx, bnh, bnl,
            pn_ln_g + i*HH, pn_ln_b + i*HH, nullptr, LL);
        mma_conv<3><<<dim3(LL/128, HH2/64, BB), blk, SM3>>>(bnh, bnl,
            wh + OW_P1 + (size_t)i*HH2*HH*3, wl + OW_P1 + (size_t)i*HH2*HH*3,
            pn_b1 + i*HH2, nullptr, 0, bmh, bml, nullptr, nullptr, HH, HH2, LL, scale, 1);
        mma_conv<1><<<dim3(LL/128, HH/64, BB), blk, SM1>>>(bmh, bml,
            wh + OW_P2 + (size_t)i*HH*HH2, wl + OW_P2 + (size_t)i*HH*HH2,
            pn_b2 + i*HH, bx, 1, nullptr, nullptr, bx, ph_mask, HH2, HH, LL, 1.f, 0);
    }
    ln_kernel<<<(BB*LL)/8, 256>>>(bx, bnh, bnl, pn_last_g, pn_last_b, ph_mask, LL);
    mma_conv<3><<<dim3(LL/128, HH/64, BB), blk, SM3>>>(bnh, bnl, wh + OW_PP, wl + OW_PP,
        pn_post_b, nullptr, 0, byh, byl, nullptr, ph_mask, HH, HH, LL, 1.f, 0);

    // ---- proj_in -> VQ -> proj_out ----
    mma_conv<1><<<dim3(LL/128, 1, BB), blk, SM1>>>(byh, byl, wh + OW_PI, wl + OW_PI,
        proj_in_b, bz, 1, nullptr, nullptr, nullptr, nullptr, HH, CVQd, LL, 1.f, 0);
    vq_kernel<<<dim3(LL, BB), 128>>>(bz, codebook, qh, ql, out + (size_t)BB*HH*LL + 1, loss);
    mma_conv<1><<<dim3(LL/128, HH/64, BB), blk, SM1>>>(qh, ql, wh + OW_PO, wl + OW_PO,
        proj_out_b, out, 0, nullptr, nullptr, nullptr, nullptr, CVQd, HH, LL, 1.f, 0);
    loss_fin<<<1, 1>>>(loss, out + (size_t)BB*HH*LL);
}